// round 13
// baseline (speedup 1.0000x reference)
#include <cuda_runtime.h>
#include <cuda_bf16.h>
#include <math.h>

#define NNODE 5000
#define NEDGE 50000
#define FDIM 64

// ---------------- device scratch ----------------
__device__ float g0buf[NNODE * 64];
__device__ float g1buf[NNODE * 192];   // [n][c(3)][f(64)]
__device__ float g2buf[NNODE * 320];   // [n][c(5)][f(64)]
__device__ float abuf[NNODE * 2752];   // [n][ a0(192) | a1(960) | a2(1600) ]
__device__ float d_CG[504];

#define OFF110 0
#define OFF220 9
#define OFF121 34
#define OFF211 79
#define OFF231 124
#define OFF112 229
#define OFF132 274
#define OFF222 379

// factorials and their inverses (exact in fp64 for n<=9)
__constant__ double c_F[10]   = {1., 1., 2., 6., 24., 120., 720., 5040., 40320., 362880.};
__constant__ double c_INV[10] = {1., 1., 1.0/2., 1.0/6., 1.0/24., 1.0/120., 1.0/720.,
                                 1.0/5040., 1.0/40320., 1.0/362880.};

// CG coefficient, division-free inner loop
__device__ double cgc_fast(int j1, int m1, int j2, int m2, int j3, int m3) {
    if (m1 + m2 != m3) return 0.0;
    int lo = j1 - j2; if (lo < 0) lo = -lo;
    if (j3 < lo || j3 > j1 + j2) return 0.0;
    double pref = sqrt((2.0 * j3 + 1.0) * c_F[j3 + j1 - j2] * c_F[j3 - j1 + j2] *
                       c_F[j1 + j2 - j3] * c_INV[j1 + j2 + j3 + 1]);
    pref *= sqrt(c_F[j3 + m3] * c_F[j3 - m3] * c_F[j1 - m1] * c_F[j1 + m1] *
                 c_F[j2 - m2] * c_F[j2 + m2]);
    double s = 0.0;
    for (int k = 0; k <= j1 + j2 + j3; k++) {
        int d0 = j1 + j2 - j3 - k, d1 = j1 - m1 - k, d2 = j2 + m2 - k;
        int d3 = j3 - j2 + m1 + k, d4 = j3 - j1 - m2 + k;
        if (d0 < 0 || d1 < 0 || d2 < 0 || d3 < 0 || d4 < 0) continue;
        double term = c_INV[k] * c_INV[d0] * c_INV[d1] * c_INV[d2] * c_INV[d3] * c_INV[d4];
        s += (k & 1) ? -term : term;
    }
    return pref * s;
}

__device__ double2 Umat(int l, int i, int a) {
    const double s = 0.70710678118654752440;
    int mi = i - l;
    if (mi == 0) return (a == l) ? make_double2(1.0, 0.0) : make_double2(0.0, 0.0);
    if (mi > 0) {
        int m = mi; double sgn = (m & 1) ? -1.0 : 1.0;
        if (a == l + m) return make_double2(sgn * s, 0.0);
        if (a == l - m) return make_double2(s, 0.0);
    } else {
        int m = -mi; double sgn = (m & 1) ? -1.0 : 1.0;
        if (a == l - m) return make_double2(0.0, s);
        if (a == l + m) return make_double2(0.0, -sgn * s);
    }
    return make_double2(0.0, 0.0);
}

// ---------------- fused init: warp-parallel CG + zero accumulators ----------------
__global__ void init_kernel() {
    int warp_gid = blockIdx.x * 8 + (threadIdx.x >> 5);
    int lane = threadIdx.x & 31;

    if (warp_gid < 504) {
        int idx = warp_gid;
        int l1, l2, l3, flat;
        if (idx < 9)        { l1 = 1; l2 = 1; l3 = 0; flat = idx; }
        else if (idx < 34)  { l1 = 2; l2 = 2; l3 = 0; flat = idx - 9; }
        else if (idx < 79)  { l1 = 1; l2 = 2; l3 = 1; flat = idx - 34; }
        else if (idx < 124) { l1 = 2; l2 = 1; l3 = 1; flat = idx - 79; }
        else if (idx < 229) { l1 = 2; l2 = 3; l3 = 1; flat = idx - 124; }
        else if (idx < 274) { l1 = 1; l2 = 1; l3 = 2; flat = idx - 229; }
        else if (idx < 379) { l1 = 1; l2 = 3; l3 = 2; flat = idx - 274; }
        else                { l1 = 2; l2 = 2; l3 = 2; flat = idx - 379; }
        int dd2 = 2 * l2 + 1, dd3 = 2 * l3 + 1;
        int i = flat / (dd2 * dd3), j = (flat / dd3) % dd2, k = flat % dd3;

        int d1 = 2 * l1 + 1, d2 = 2 * l2 + 1, d3 = 2 * l3 + 1;
        double re = 0.0;
        for (int ab = lane; ab < d1 * d2; ab += 32) {
            int a = ab / d2, b = ab % d2;
            double2 u1 = Umat(l1, i, a);
            if (u1.x == 0.0 && u1.y == 0.0) continue;
            double2 u2 = Umat(l2, j, b);
            if (u2.x == 0.0 && u2.y == 0.0) continue;
            double pr = u1.x * u2.x - u1.y * u2.y;
            double pi = u1.x * u2.y + u1.y * u2.x;
            for (int c = 0; c < d3; c++) {
                double2 u3 = Umat(l3, k, c);
                u3.y = -u3.y;  // conj
                if (u3.x == 0.0 && u3.y == 0.0) continue;
                double cg = cgc_fast(l1, a - l1, l2, b - l2, l3, c - l3);
                if (cg == 0.0) continue;
                re += (pr * u3.x - pi * u3.y) * cg;
            }
        }
        __syncwarp();
#pragma unroll
        for (int off = 16; off > 0; off >>= 1)
            re += __shfl_xor_sync(0xffffffffu, re, off);
        if (lane == 0) d_CG[idx] = (float)re;
    }

    // all blocks: zero accumulators
    float4* p = reinterpret_cast<float4*>(abuf);
    int n4 = NNODE * 2752 / 4;
    int gid = blockIdx.x * blockDim.x + threadIdx.x;
    int stride = gridDim.x * blockDim.x;
    float4 z = make_float4(0.f, 0.f, 0.f, 0.f);
    for (int q = gid; q < n4; q += stride) p[q] = z;
}

__device__ __forceinline__ float swishf(float x) {
    return x / (1.0f + __expf(-x));
}

// ---------------- node prep v2: 8 nodes / block, 256 threads ----------------
// group g (of 4) register-blocks local nodes 2g, 2g+1; each weight LDG feeds 8 nodes.
// two passes (l0+l1, then l2) to bound register pressure.
__global__ void __launch_bounds__(256) node_prep_kernel(
        const float* __restrict__ nf,
        const int* __restrict__ specie,
        const float* __restrict__ Wsc0, const float* __restrict__ Wsc1,
        const float* __restrict__ Wsc2, const float* __restrict__ Wu0,
        const float* __restrict__ Wu1, const float* __restrict__ Wu2,
        float* __restrict__ out) {
    __shared__ float sf[8 * 576];
    int t = threadIdx.x;
    int ft = t & 63;
    int g = t >> 6;
    int nb = blockIdx.x * 8;

    // coalesced load of 8 contiguous node-feature rows (8*576 = 4608 floats)
    {
        const float4* src = (const float4*)(nf + (size_t)nb * 576);
        float4* dst = (float4*)sf;
        for (int i = t; i < 1152; i += 256) dst[i] = src[i];
    }
    __syncthreads();

    const float invF = 0.125f;  // 1/sqrt(64)
    int n0 = nb + 2 * g, n1 = nb + 2 * g + 1;
    const float* s0p = sf + (2 * g + 0) * 576;
    const float* s1p = sf + (2 * g + 1) * 576;
    float* orow0 = out + (size_t)n0 * 576;
    float* orow1 = out + (size_t)n1 * 576;

    // ---- pass 1: l=0 and l=1 (sc0,g0,sc1,g1) ----
    {
        float sc0[2] = {0.f, 0.f}, g0[2] = {0.f, 0.f};
        float sc1[3][2] = {}, g1[3][2] = {};
#pragma unroll 4
        for (int f = 0; f < 64; f++) {
            float w0 = Wsc0[f * 64 + ft], u0 = Wu0[f * 64 + ft];
            float w1 = Wsc1[f * 64 + ft], u1 = Wu1[f * 64 + ft];
            float v0a = s0p[f], v0b = s1p[f];
            sc0[0] = fmaf(v0a, w0, sc0[0]); g0[0] = fmaf(v0a, u0, g0[0]);
            sc0[1] = fmaf(v0b, w0, sc0[1]); g0[1] = fmaf(v0b, u0, g0[1]);
#pragma unroll
            for (int c = 0; c < 3; c++) {
                float va = s0p[64 + f * 3 + c], vb = s1p[64 + f * 3 + c];
                sc1[c][0] = fmaf(va, w1, sc1[c][0]); g1[c][0] = fmaf(va, u1, g1[c][0]);
                sc1[c][1] = fmaf(vb, w1, sc1[c][1]); g1[c][1] = fmaf(vb, u1, g1[c][1]);
            }
        }
        orow0[ft] = sc0[0] * invF;
        orow1[ft] = sc0[1] * invF;
        g0buf[n0 * 64 + ft] = g0[0] * invF;
        g0buf[n1 * 64 + ft] = g0[1] * invF;
#pragma unroll
        for (int c = 0; c < 3; c++) {
            orow0[64 + ft * 3 + c] = sc1[c][0] * invF;
            orow1[64 + ft * 3 + c] = sc1[c][1] * invF;
            g1buf[n0 * 192 + c * 64 + ft] = g1[c][0] * invF;
            g1buf[n1 * 192 + c * 64 + ft] = g1[c][1] * invF;
        }
    }

    // ---- pass 2: l=2 (sc2,g2) ----
    {
        float sc2[5][2] = {}, g2[5][2] = {};
#pragma unroll 4
        for (int f = 0; f < 64; f++) {
            float w2 = Wsc2[f * 64 + ft], u2 = Wu2[f * 64 + ft];
#pragma unroll
            for (int c = 0; c < 5; c++) {
                float va = s0p[256 + f * 5 + c], vb = s1p[256 + f * 5 + c];
                sc2[c][0] = fmaf(va, w2, sc2[c][0]); g2[c][0] = fmaf(va, u2, g2[c][0]);
                sc2[c][1] = fmaf(vb, w2, sc2[c][1]); g2[c][1] = fmaf(vb, u2, g2[c][1]);
            }
        }
#pragma unroll
        for (int c = 0; c < 5; c++) {
            orow0[256 + ft * 5 + c] = sc2[c][0] * invF;
            orow1[256 + ft * 5 + c] = sc2[c][1] * invF;
            g2buf[n0 * 320 + c * 64 + ft] = g2[c][0] * invF;
            g2buf[n1 * 320 + c * 64 + ft] = g2[c][1] * invF;
        }
    }
}

// ---------------- edge kernel (round-7 proven version) ----------------
__global__ void __launch_bounds__(256, 4) edge_kernel(const float* __restrict__ vectors,
                            const int* __restrict__ senders,
                            const int* __restrict__ receivers,
                            const float* __restrict__ Wm1,
                            const float* __restrict__ Wm2,
                            const float* __restrict__ Wm3) {
    __shared__ float h1[64 * 20];
    __shared__ float h2[64 * 20];
    __shared__ float sT[16 * 104];
    __shared__ float ssh[16 * 16];
    __shared__ float sradT[8 * 16];
    __shared__ float sx[16], sinvx[16];
    __shared__ int ssend[16], srecv[16], sact[16];

    int t = threadIdx.x;
    int ft = t & 63;
    int g = t >> 6;
    int e0 = blockIdx.x * 16;

    if (t < 16) {
        int e = e0 + t;
        float vx = vectors[e * 3 + 0], vy = vectors[e * 3 + 1], vz = vectors[e * 3 + 2];
        float x = sqrtf(fmaxf(vx * vx + vy * vy + vz * vz, 1e-12f));
        float invx = 1.0f / x;
        float ux = vx * invx, uy = vy * invx, uz = vz * invx;
        sx[t] = x; sinvx[t] = invx;
        sact[t] = (x < 1.0f) ? 1 : 0;
        ssend[t] = senders[e];
        srecv[t] = receivers[e];
        float* sh = ssh + t * 16;
        const float s3 = 1.7320508075688772f;
        const float s15 = 3.872983346207417f;
        const float s5 = 2.23606797749979f;
        const float c35 = 2.091650066335189f;
        const float c105 = 10.246950765959598f;
        const float c21 = 1.6201851746019651f;
        const float c7 = 1.3228756555322954f;
        sh[0] = s3 * uy; sh[1] = s3 * uz; sh[2] = s3 * ux;
        sh[3] = s15 * ux * uy;
        sh[4] = s15 * uy * uz;
        sh[5] = 0.5f * s5 * (3.0f * uz * uz - 1.0f);
        sh[6] = s15 * ux * uz;
        sh[7] = 0.5f * s15 * (ux * ux - uy * uy);
        sh[8]  = c35 * uy * (3.0f * ux * ux - uy * uy);
        sh[9]  = c105 * ux * uy * uz;
        sh[10] = c21 * uy * (5.0f * uz * uz - 1.0f);
        sh[11] = c7 * uz * (5.0f * uz * uz - 3.0f);
        sh[12] = c21 * ux * (5.0f * uz * uz - 1.0f);
        sh[13] = 0.5f * c105 * uz * (ux * ux - uy * uy);
        sh[14] = c35 * ux * (ux * ux - 3.0f * uy * uy);
        sh[15] = 0.f;
    }
    __syncthreads();

    if (t < 128) {
        int e = t & 15, n = t >> 4;
        float x = sx[e];
        float env = 0.f;
        if (x < 1.0f) {
            float x2 = x * x, x4 = x2 * x2, x6 = x4 * x2, x7 = x6 * x, x8 = x7 * x;
            env = 1.0f - 28.0f * x6 + 48.0f * x7 - 21.0f * x8;
        }
        float nn = (float)(n + 1);
        sradT[n * 16 + e] = 1.41421356237f * sinf(3.14159265358979f * nn * x) * sinvx[e] * env;
    }
    __syncthreads();

    for (int idx = t; idx < 16 * 102; idx += 256) {
        int e = idx / 102, j = idx % 102;
        const float* sh = ssh + e * 16;
        float v = 0.f;
        if (j < 3) {
            int i = j;
            for (int q = 0; q < 3; q++) v = fmaf(sh[q], d_CG[OFF110 + i * 3 + q], v);
        } else if (j < 8) {
            int i = j - 3;
            for (int q = 0; q < 5; q++) v = fmaf(sh[3 + q], d_CG[OFF220 + i * 5 + q], v);
        } else if (j < 17) {
            int ee = j - 8; int i = ee / 3, k = ee % 3;
            for (int q = 0; q < 5; q++) v = fmaf(sh[3 + q], d_CG[OFF121 + (i * 5 + q) * 3 + k], v);
        } else if (j < 32) {
            int ee = j - 17; int i = ee / 3, k = ee % 3;
            for (int q = 0; q < 3; q++) v = fmaf(sh[q], d_CG[OFF211 + (i * 3 + q) * 3 + k], v);
        } else if (j < 47) {
            int ee = j - 32; int i = ee / 3, k = ee % 3;
            for (int q = 0; q < 7; q++) v = fmaf(sh[8 + q], d_CG[OFF231 + (i * 7 + q) * 3 + k], v);
        } else if (j < 62) {
            int ee = j - 47; int i = ee / 5, k = ee % 5;
            for (int q = 0; q < 3; q++) v = fmaf(sh[q], d_CG[OFF112 + (i * 3 + q) * 5 + k], v);
        } else if (j < 77) {
            int ee = j - 62; int i = ee / 5, k = ee % 5;
            for (int q = 0; q < 7; q++) v = fmaf(sh[8 + q], d_CG[OFF132 + (i * 7 + q) * 5 + k], v);
        } else {
            int ee = j - 77; int i = ee / 5, k = ee % 5;
            for (int q = 0; q < 5; q++) v = fmaf(sh[3 + q], d_CG[OFF222 + (i * 5 + q) * 5 + k], v);
        }
        sT[e * 104 + j] = v;
    }
    __syncthreads();

    {
        float a0 = 0.f, a1 = 0.f, a2 = 0.f, a3 = 0.f;
#pragma unroll
        for (int i = 0; i < 8; i++) {
            float w = Wm1[i * 64 + ft];
            float4 r = *(const float4*)(sradT + i * 16 + 4 * g);
            a0 = fmaf(r.x, w, a0); a1 = fmaf(r.y, w, a1);
            a2 = fmaf(r.z, w, a2); a3 = fmaf(r.w, w, a3);
        }
        const float s8 = 0.35355339059327f;
        h1[ft * 20 + 4 * g + 0] = swishf(a0 * s8);
        h1[ft * 20 + 4 * g + 1] = swishf(a1 * s8);
        h1[ft * 20 + 4 * g + 2] = swishf(a2 * s8);
        h1[ft * 20 + 4 * g + 3] = swishf(a3 * s8);
    }
    __syncthreads();

    {
        float a0 = 0.f, a1 = 0.f, a2 = 0.f, a3 = 0.f;
#pragma unroll 8
        for (int f = 0; f < 64; f++) {
            float w = Wm2[f * 64 + ft];
            float4 hv = *(const float4*)(h1 + f * 20 + 4 * g);
            a0 = fmaf(hv.x, w, a0); a1 = fmaf(hv.y, w, a1);
            a2 = fmaf(hv.z, w, a2); a3 = fmaf(hv.w, w, a3);
        }
        const float s64 = 0.125f;
        h2[ft * 20 + 4 * g + 0] = swishf(a0 * s64);
        h2[ft * 20 + 4 * g + 1] = swishf(a1 * s64);
        h2[ft * 20 + 4 * g + 2] = swishf(a2 * s64);
        h2[ft * 20 + 4 * g + 3] = swishf(a3 * s64);
    }
    __syncthreads();

    const float msc = 0.125f * 0.316227766016838f;

    // PASS A: channels {0,1,3,4,5,9,10,11} (s0/s1)
    {
        float acc[8][4];
#pragma unroll
        for (int q = 0; q < 8; q++)
#pragma unroll
            for (int el = 0; el < 4; el++) acc[q][el] = 0.f;
#pragma unroll 2
        for (int f = 0; f < 64; f++) {
            float4 hv = *(const float4*)(h2 + f * 20 + 4 * g);
            const float* wrow = Wm3 + f * 832 + ft;
            float w;
#define FMA4(Q, M)                                            \
            w = wrow[(M) * 64];                               \
            acc[Q][0] = fmaf(hv.x, w, acc[Q][0]);             \
            acc[Q][1] = fmaf(hv.y, w, acc[Q][1]);             \
            acc[Q][2] = fmaf(hv.z, w, acc[Q][2]);             \
            acc[Q][3] = fmaf(hv.w, w, acc[Q][3]);
            FMA4(0, 0) FMA4(1, 1) FMA4(2, 3) FMA4(3, 4)
            FMA4(4, 5) FMA4(5, 9) FMA4(6, 10) FMA4(7, 11)
#undef FMA4
        }
#pragma unroll
        for (int q = 0; q < 8; q++)
#pragma unroll
            for (int el = 0; el < 4; el++) acc[q][el] *= msc;

#pragma unroll
        for (int el = 0; el < 4; el++) {
            int e = 4 * g + el;
            if (!sact[e]) continue;
            int sn = ssend[e];
            float* ap = abuf + (size_t)srecv[e] * 2752;
            const float* T = sT + e * 104;
            const float* sh = ssh + e * 16;
            float s0v = g0buf[sn * 64 + ft];
            float s1a = g1buf[sn * 192 + 0 * 64 + ft];
            float s1b = g1buf[sn * 192 + 1 * 64 + ft];
            float s1c = g1buf[sn * 192 + 2 * 64 + ft];

            atomicAdd(ap + ft, s0v * acc[0][el]);
            float tp110 = s1a * T[0] + s1b * T[1] + s1c * T[2];
            atomicAdd(ap + 64 + ft, tp110 * acc[1][el]);
#pragma unroll
            for (int c = 0; c < 3; c++) {
                float* p = ap + 192 + c * 320;
                float s1cc = (c == 0) ? s1a : ((c == 1) ? s1b : s1c);
                atomicAdd(p + ft, s1cc * acc[2][el]);
                atomicAdd(p + 64 + ft, s0v * sh[c] * acc[3][el]);
                float t121 = s1a * T[8 + c] + s1b * T[11 + c] + s1c * T[14 + c];
                atomicAdd(p + 128 + ft, t121 * acc[4][el]);
            }
#pragma unroll
            for (int c = 0; c < 5; c++) {
                float* p = ap + 1152 + c * 320;
                atomicAdd(p + 64 + ft, s0v * sh[3 + c] * acc[5][el]);
                float t112 = s1a * T[47 + c] + s1b * T[52 + c] + s1c * T[57 + c];
                atomicAdd(p + 128 + ft, t112 * acc[6][el]);
                float t132 = s1a * T[62 + c] + s1b * T[67 + c] + s1c * T[72 + c];
                atomicAdd(p + 192 + ft, t132 * acc[7][el]);
            }
        }
    }

    // PASS B: channels {2,6,7,8,12} (s2)
    {
        float acc[5][4];
#pragma unroll
        for (int q = 0; q < 5; q++)
#pragma unroll
            for (int el = 0; el < 4; el++) acc[q][el] = 0.f;
#pragma unroll 2
        for (int f = 0; f < 64; f++) {
            float4 hv = *(const float4*)(h2 + f * 20 + 4 * g);
            const float* wrow = Wm3 + f * 832 + ft;
            float w;
#define FMA4(Q, M)                                            \
            w = wrow[(M) * 64];                               \
            acc[Q][0] = fmaf(hv.x, w, acc[Q][0]);             \
            acc[Q][1] = fmaf(hv.y, w, acc[Q][1]);             \
            acc[Q][2] = fmaf(hv.z, w, acc[Q][2]);             \
            acc[Q][3] = fmaf(hv.w, w, acc[Q][3]);
            FMA4(0, 2) FMA4(1, 6) FMA4(2, 7) FMA4(3, 8) FMA4(4, 12)
#undef FMA4
        }
#pragma unroll
        for (int q = 0; q < 5; q++)
#pragma unroll
            for (int el = 0; el < 4; el++) acc[q][el] *= msc;

#pragma unroll
        for (int el = 0; el < 4; el++) {
            int e = 4 * g + el;
            if (!sact[e]) continue;
            int sn = ssend[e];
            float* ap = abuf + (size_t)srecv[e] * 2752;
            const float* T = sT + e * 104;
            float s2v[5];
#pragma unroll
            for (int c = 0; c < 5; c++) s2v[c] = g2buf[sn * 320 + c * 64 + ft];

            float tp220 = 0.f;
#pragma unroll
            for (int i = 0; i < 5; i++) tp220 = fmaf(s2v[i], T[3 + i], tp220);
            atomicAdd(ap + 128 + ft, tp220 * acc[0][el]);

#pragma unroll
            for (int c = 0; c < 3; c++) {
                float* p = ap + 192 + c * 320;
                float t211 = 0.f, t231 = 0.f;
#pragma unroll
                for (int i = 0; i < 5; i++) {
                    t211 = fmaf(s2v[i], T[17 + i * 3 + c], t211);
                    t231 = fmaf(s2v[i], T[32 + i * 3 + c], t231);
                }
                atomicAdd(p + 192 + ft, t211 * acc[1][el]);
                atomicAdd(p + 256 + ft, t231 * acc[2][el]);
            }
#pragma unroll
            for (int c = 0; c < 5; c++) {
                float* p = ap + 1152 + c * 320;
                atomicAdd(p + ft, s2v[c] * acc[3][el]);
                float t222 = 0.f;
#pragma unroll
                for (int i = 0; i < 5; i++) t222 = fmaf(s2v[i], T[77 + i * 5 + c], t222);
                atomicAdd(p + 256 + ft, t222 * acc[4][el]);
            }
        }
    }
}

// ---------------- node output: 4 nodes / block, 320 threads (round-7 proven version) ----------------
__global__ void __launch_bounds__(320) node_out_kernel(const float* __restrict__ Wd0,
                                const float* __restrict__ Wd1,
                                const float* __restrict__ Wd2,
                                float* __restrict__ out) {
    int n0 = blockIdx.x * 4;
    int t = threadIdx.x;
    __shared__ float saT[2752 * 4];
    __shared__ float sd0[4 * 192];

    for (int j = t; j < 2752; j += 320) {
#pragma unroll
        for (int nn = 0; nn < 4; nn++)
            saT[j * 4 + nn] = abuf[(size_t)(n0 + nn) * 2752 + j];
    }
    __syncthreads();

    if (t < 192) {
        float a0 = 0.f, a1 = 0.f, a2 = 0.f, a3 = 0.f;
#pragma unroll 8
        for (int m = 0; m < 192; m++) {
            float w = Wd0[m * 192 + t];
            float4 av = *(const float4*)(saT + m * 4);
            a0 = fmaf(av.x, w, a0); a1 = fmaf(av.y, w, a1);
            a2 = fmaf(av.z, w, a2); a3 = fmaf(av.w, w, a3);
        }
        const float s = 0.0721687836487032f;
        sd0[0 * 192 + t] = swishf(a0 * s);
        sd0[1 * 192 + t] = swishf(a1 * s);
        sd0[2 * 192 + t] = swishf(a2 * s);
        sd0[3 * 192 + t] = swishf(a3 * s);
    }
    __syncthreads();

    if (t < 64) {
#pragma unroll
        for (int nn = 0; nn < 4; nn++)
            out[(size_t)(n0 + nn) * 576 + t] += sd0[nn * 192 + t];
    }

    const float s320 = 0.0559016994374947f;

    if (t < 192) {
        int c = t / 64, f = t % 64;
        float a0 = 0.f, a1 = 0.f, a2 = 0.f, a3 = 0.f;
        const float* base = saT + (192 + c * 320) * 4;
#pragma unroll 8
        for (int m = 0; m < 320; m++) {
            float w = Wd1[m * 64 + f];
            float4 av = *(const float4*)(base + m * 4);
            a0 = fmaf(av.x, w, a0); a1 = fmaf(av.y, w, a1);
            a2 = fmaf(av.z, w, a2); a3 = fmaf(av.w, w, a3);
        }
        float r[4] = {a0, a1, a2, a3};
#pragma unroll
        for (int nn = 0; nn < 4; nn++)
            out[(size_t)(n0 + nn) * 576 + 64 + f * 3 + c] += r[nn] * s320 * sd0[nn * 192 + 64 + f];
    }

    {
        int c = t / 64, f = t % 64;
        float a0 = 0.f, a1 = 0.f, a2 = 0.f, a3 = 0.f;
        const float* base = saT + (1152 + c * 320) * 4;
#pragma unroll 8
        for (int m = 0; m < 320; m++) {
            float w = Wd2[m * 64 + f];
            float4 av = *(const float4*)(base + m * 4);
            a0 = fmaf(av.x, w, a0); a1 = fmaf(av.y, w, a1);
            a2 = fmaf(av.z, w, a2); a3 = fmaf(av.w, w, a3);
        }
        float r[4] = {a0, a1, a2, a3};
#pragma unroll
        for (int nn = 0; nn < 4; nn++)
            out[(size_t)(n0 + nn) * 576 + 256 + f * 5 + c] += r[nn] * s320 * sd0[nn * 192 + 128 + f];
    }
}

// ---------------- launcher ----------------
extern "C" void kernel_launch(void* const* d_in, const int* in_sizes, int n_in,
                              void* d_out, int out_size) {
    const float* vectors    = (const float*)d_in[0];
    const float* node_feats = (const float*)d_in[1];
    const int*   node_specie= (const int*)d_in[2];
    const int*   senders    = (const int*)d_in[3];
    const int*   receivers  = (const int*)d_in[4];
    const float* Wsc0 = (const float*)d_in[5];
    const float* Wsc1 = (const float*)d_in[6];
    const float* Wsc2 = (const float*)d_in[7];
    const float* Wu0  = (const float*)d_in[8];
    const float* Wu1  = (const float*)d_in[9];
    const float* Wu2  = (const float*)d_in[10];
    const float* Wm1  = (const float*)d_in[11];
    const float* Wm2  = (const float*)d_in[12];
    const float* Wm3  = (const float*)d_in[13];
    const float* Wd0  = (const float*)d_in[14];
    const float* Wd1  = (const float*)d_in[15];
    const float* Wd2  = (const float*)d_in[16];
    float* out = (float*)d_out;

    init_kernel<<<2048, 256>>>();
    node_prep_kernel<<<NNODE / 8, 256>>>(node_feats, node_specie, Wsc0, Wsc1, Wsc2,
                                         Wu0, Wu1, Wu2, out);
    edge_kernel<<<NEDGE / 16, 256>>>(vectors, senders, receivers, Wm1, Wm2, Wm3);
    node_out_kernel<<<NNODE / 4, 320>>>(Wd0, Wd1, Wd2, out);
}

// round 14
// speedup vs baseline: 1.0469x; 1.0469x over previous
#include <cuda_runtime.h>
#include <cuda_bf16.h>
#include <math.h>

#define NNODE 5000
#define NEDGE 50000
#define FDIM 64

// ---------------- device scratch ----------------
__device__ float g0buf[NNODE * 64];
__device__ float g1buf[NNODE * 192];   // [n][c(3)][f(64)]
__device__ float g2buf[NNODE * 320];   // [n][c(5)][f(64)]
__device__ float abuf[NNODE * 2752];   // [n][ a0(192) | a1(960) | a2(1600) ]
__device__ float d_CG[504];

#define OFF110 0
#define OFF220 9
#define OFF121 34
#define OFF211 79
#define OFF231 124
#define OFF112 229
#define OFF132 274
#define OFF222 379

// factorials and inverses (exact in fp64 for n<=9)
__constant__ double c_F[10]   = {1., 1., 2., 6., 24., 120., 720., 5040., 40320., 362880.};
__constant__ double c_INV[10] = {1., 1., 1.0/2., 1.0/6., 1.0/24., 1.0/120., 1.0/720.,
                                 1.0/5040., 1.0/40320., 1.0/362880.};

__device__ double cgc_fast(int j1, int m1, int j2, int m2, int j3, int m3) {
    if (m1 + m2 != m3) return 0.0;
    int lo = j1 - j2; if (lo < 0) lo = -lo;
    if (j3 < lo || j3 > j1 + j2) return 0.0;
    double pref = sqrt((2.0 * j3 + 1.0) * c_F[j3 + j1 - j2] * c_F[j3 - j1 + j2] *
                       c_F[j1 + j2 - j3] * c_INV[j1 + j2 + j3 + 1]);
    pref *= sqrt(c_F[j3 + m3] * c_F[j3 - m3] * c_F[j1 - m1] * c_F[j1 + m1] *
                 c_F[j2 - m2] * c_F[j2 + m2]);
    double s = 0.0;
    for (int k = 0; k <= j1 + j2 + j3; k++) {
        int d0 = j1 + j2 - j3 - k, d1 = j1 - m1 - k, d2 = j2 + m2 - k;
        int d3 = j3 - j2 + m1 + k, d4 = j3 - j1 - m2 + k;
        if (d0 < 0 || d1 < 0 || d2 < 0 || d3 < 0 || d4 < 0) continue;
        double term = c_INV[k] * c_INV[d0] * c_INV[d1] * c_INV[d2] * c_INV[d3] * c_INV[d4];
        s += (k & 1) ? -term : term;
    }
    return pref * s;
}

__device__ double2 Umat(int l, int i, int a) {
    const double s = 0.70710678118654752440;
    int mi = i - l;
    if (mi == 0) return (a == l) ? make_double2(1.0, 0.0) : make_double2(0.0, 0.0);
    if (mi > 0) {
        int m = mi; double sgn = (m & 1) ? -1.0 : 1.0;
        if (a == l + m) return make_double2(sgn * s, 0.0);
        if (a == l - m) return make_double2(s, 0.0);
    } else {
        int m = -mi; double sgn = (m & 1) ? -1.0 : 1.0;
        if (a == l - m) return make_double2(0.0, s);
        if (a == l + m) return make_double2(0.0, -sgn * s);
    }
    return make_double2(0.0, 0.0);
}

__device__ __forceinline__ float swishf(float x) {
    return x / (1.0f + __expf(-x));
}

// ---------------- fused: CG init + zero accumulators + node_prep ----------------
// blocks 0..62          : CG (8 warps each, 504 warps) + zero share
// blocks 63..1312       : node_prep, 4 nodes/block (R7-proven per-node logic)
// blocks 1313..2047     : zero share
#define FUSED_BLOCKS 2048
#define PREP_FIRST 63
#define PREP_COUNT 1250

__global__ void __launch_bounds__(256) fused_prep_kernel(
        const float* __restrict__ nf,
        const int* __restrict__ specie,
        const float* __restrict__ Wsc0, const float* __restrict__ Wsc1,
        const float* __restrict__ Wsc2, const float* __restrict__ Wu0,
        const float* __restrict__ Wu1, const float* __restrict__ Wu2,
        float* __restrict__ out) {
    int b = blockIdx.x;
    int t = threadIdx.x;

    if (b >= PREP_FIRST && b < PREP_FIRST + PREP_COUNT) {
        // ---------- node_prep: 4 nodes per block ----------
        __shared__ float sf[4 * 576];
        int nb = (b - PREP_FIRST) * 4;
        {
            const float4* src = (const float4*)(nf + (size_t)nb * 576);
            float4* dst = (float4*)sf;
            for (int i = t; i < 576; i += 256) dst[i] = src[i];
        }
        __syncthreads();

        int g = t & 63;          // feature index within node
        int ln = t >> 6;         // local node 0..3
        int n = nb + ln;
        const float* sfp = sf + ln * 576;
        int sp = specie[n];
        const float* w0p = Wsc0 + sp * 4096;
        const float* w1p = Wsc1 + sp * 4096;
        const float* w2p = Wsc2 + sp * 4096;

        float sc0 = 0.f, g0 = 0.f;
        float sc1[3] = {0.f, 0.f, 0.f}, g1[3] = {0.f, 0.f, 0.f};
        float sc2[5] = {0.f, 0.f, 0.f, 0.f, 0.f}, g2[5] = {0.f, 0.f, 0.f, 0.f, 0.f};
#pragma unroll 4
        for (int f = 0; f < 64; f++) {
            float w0 = w0p[f * 64 + g], u0 = Wu0[f * 64 + g];
            float w1 = w1p[f * 64 + g], u1 = Wu1[f * 64 + g];
            float w2 = w2p[f * 64 + g], u2 = Wu2[f * 64 + g];
            float v0 = sfp[f];
            sc0 = fmaf(v0, w0, sc0);
            g0  = fmaf(v0, u0, g0);
#pragma unroll
            for (int c = 0; c < 3; c++) {
                float v = sfp[64 + f * 3 + c];
                sc1[c] = fmaf(v, w1, sc1[c]);
                g1[c]  = fmaf(v, u1, g1[c]);
            }
#pragma unroll
            for (int c = 0; c < 5; c++) {
                float v = sfp[256 + f * 5 + c];
                sc2[c] = fmaf(v, w2, sc2[c]);
                g2[c]  = fmaf(v, u2, g2[c]);
            }
        }
        const float invF = 0.125f;
        float* orow = out + (size_t)n * 576;
        orow[g] = sc0 * invF;
#pragma unroll
        for (int c = 0; c < 3; c++) orow[64 + g * 3 + c] = sc1[c] * invF;
#pragma unroll
        for (int c = 0; c < 5; c++) orow[256 + g * 5 + c] = sc2[c] * invF;
        g0buf[n * 64 + g] = g0 * invF;
#pragma unroll
        for (int c = 0; c < 3; c++) g1buf[n * 192 + c * 64 + g] = g1[c] * invF;
#pragma unroll
        for (int c = 0; c < 5; c++) g2buf[n * 320 + c * 64 + g] = g2[c] * invF;
        return;
    }

    // ---------- CG (blocks 0..62) ----------
    if (b < PREP_FIRST) {
        int warp_gid = b * 8 + (t >> 5);
        int lane = t & 31;
        if (warp_gid < 504) {
            int idx = warp_gid;
            int l1, l2, l3, flat;
            if (idx < 9)        { l1 = 1; l2 = 1; l3 = 0; flat = idx; }
            else if (idx < 34)  { l1 = 2; l2 = 2; l3 = 0; flat = idx - 9; }
            else if (idx < 79)  { l1 = 1; l2 = 2; l3 = 1; flat = idx - 34; }
            else if (idx < 124) { l1 = 2; l2 = 1; l3 = 1; flat = idx - 79; }
            else if (idx < 229) { l1 = 2; l2 = 3; l3 = 1; flat = idx - 124; }
            else if (idx < 274) { l1 = 1; l2 = 1; l3 = 2; flat = idx - 229; }
            else if (idx < 379) { l1 = 1; l2 = 3; l3 = 2; flat = idx - 274; }
            else                { l1 = 2; l2 = 2; l3 = 2; flat = idx - 379; }
            int dd2 = 2 * l2 + 1, dd3 = 2 * l3 + 1;
            int i = flat / (dd2 * dd3), j = (flat / dd3) % dd2, k = flat % dd3;

            int d1 = 2 * l1 + 1, d2 = 2 * l2 + 1, d3 = 2 * l3 + 1;
            double re = 0.0;
            for (int ab = lane; ab < d1 * d2; ab += 32) {
                int a = ab / d2, bb = ab % d2;
                double2 u1 = Umat(l1, i, a);
                if (u1.x == 0.0 && u1.y == 0.0) continue;
                double2 u2 = Umat(l2, j, bb);
                if (u2.x == 0.0 && u2.y == 0.0) continue;
                double pr = u1.x * u2.x - u1.y * u2.y;
                double pi = u1.x * u2.y + u1.y * u2.x;
                for (int c = 0; c < d3; c++) {
                    double2 u3 = Umat(l3, k, c);
                    u3.y = -u3.y;
                    if (u3.x == 0.0 && u3.y == 0.0) continue;
                    double cg = cgc_fast(l1, a - l1, l2, bb - l2, l3, c - l3);
                    if (cg == 0.0) continue;
                    re += (pr * u3.x - pi * u3.y) * cg;
                }
            }
            __syncwarp();
#pragma unroll
            for (int off = 16; off > 0; off >>= 1)
                re += __shfl_xor_sync(0xffffffffu, re, off);
            if (lane == 0) d_CG[idx] = (float)re;
        }
    }

    // ---------- zero accumulators (blocks 0..62 and 1313..2047) ----------
    int zrank = (b < PREP_FIRST) ? b : (b - PREP_COUNT);
    int zcount = FUSED_BLOCKS - PREP_COUNT;  // 798
    float4* p = reinterpret_cast<float4*>(abuf);
    int n4 = NNODE * 2752 / 4;
    int gid = zrank * 256 + t;
    int stride = zcount * 256;
    float4 z = make_float4(0.f, 0.f, 0.f, 0.f);
    for (int q = gid; q < n4; q += stride) p[q] = z;
}

// ---------------- edge kernel (round-7 proven version) ----------------
__global__ void __launch_bounds__(256, 4) edge_kernel(const float* __restrict__ vectors,
                            const int* __restrict__ senders,
                            const int* __restrict__ receivers,
                            const float* __restrict__ Wm1,
                            const float* __restrict__ Wm2,
                            const float* __restrict__ Wm3) {
    __shared__ float h1[64 * 20];
    __shared__ float h2[64 * 20];
    __shared__ float sT[16 * 104];
    __shared__ float ssh[16 * 16];
    __shared__ float sradT[8 * 16];
    __shared__ float sx[16], sinvx[16];
    __shared__ int ssend[16], srecv[16], sact[16];

    int t = threadIdx.x;
    int ft = t & 63;
    int g = t >> 6;
    int e0 = blockIdx.x * 16;

    if (t < 16) {
        int e = e0 + t;
        float vx = vectors[e * 3 + 0], vy = vectors[e * 3 + 1], vz = vectors[e * 3 + 2];
        float x = sqrtf(fmaxf(vx * vx + vy * vy + vz * vz, 1e-12f));
        float invx = 1.0f / x;
        float ux = vx * invx, uy = vy * invx, uz = vz * invx;
        sx[t] = x; sinvx[t] = invx;
        sact[t] = (x < 1.0f) ? 1 : 0;
        ssend[t] = senders[e];
        srecv[t] = receivers[e];
        float* sh = ssh + t * 16;
        const float s3 = 1.7320508075688772f;
        const float s15 = 3.872983346207417f;
        const float s5 = 2.23606797749979f;
        const float c35 = 2.091650066335189f;
        const float c105 = 10.246950765959598f;
        const float c21 = 1.6201851746019651f;
        const float c7 = 1.3228756555322954f;
        sh[0] = s3 * uy; sh[1] = s3 * uz; sh[2] = s3 * ux;
        sh[3] = s15 * ux * uy;
        sh[4] = s15 * uy * uz;
        sh[5] = 0.5f * s5 * (3.0f * uz * uz - 1.0f);
        sh[6] = s15 * ux * uz;
        sh[7] = 0.5f * s15 * (ux * ux - uy * uy);
        sh[8]  = c35 * uy * (3.0f * ux * ux - uy * uy);
        sh[9]  = c105 * ux * uy * uz;
        sh[10] = c21 * uy * (5.0f * uz * uz - 1.0f);
        sh[11] = c7 * uz * (5.0f * uz * uz - 3.0f);
        sh[12] = c21 * ux * (5.0f * uz * uz - 1.0f);
        sh[13] = 0.5f * c105 * uz * (ux * ux - uy * uy);
        sh[14] = c35 * ux * (ux * ux - 3.0f * uy * uy);
        sh[15] = 0.f;
    }
    __syncthreads();

    if (t < 128) {
        int e = t & 15, n = t >> 4;
        float x = sx[e];
        float env = 0.f;
        if (x < 1.0f) {
            float x2 = x * x, x4 = x2 * x2, x6 = x4 * x2, x7 = x6 * x, x8 = x7 * x;
            env = 1.0f - 28.0f * x6 + 48.0f * x7 - 21.0f * x8;
        }
        float nn = (float)(n + 1);
        sradT[n * 16 + e] = 1.41421356237f * sinf(3.14159265358979f * nn * x) * sinvx[e] * env;
    }
    __syncthreads();

    for (int idx = t; idx < 16 * 102; idx += 256) {
        int e = idx / 102, j = idx % 102;
        const float* sh = ssh + e * 16;
        float v = 0.f;
        if (j < 3) {
            int i = j;
            for (int q = 0; q < 3; q++) v = fmaf(sh[q], d_CG[OFF110 + i * 3 + q], v);
        } else if (j < 8) {
            int i = j - 3;
            for (int q = 0; q < 5; q++) v = fmaf(sh[3 + q], d_CG[OFF220 + i * 5 + q], v);
        } else if (j < 17) {
            int ee = j - 8; int i = ee / 3, k = ee % 3;
            for (int q = 0; q < 5; q++) v = fmaf(sh[3 + q], d_CG[OFF121 + (i * 5 + q) * 3 + k], v);
        } else if (j < 32) {
            int ee = j - 17; int i = ee / 3, k = ee % 3;
            for (int q = 0; q < 3; q++) v = fmaf(sh[q], d_CG[OFF211 + (i * 3 + q) * 3 + k], v);
        } else if (j < 47) {
            int ee = j - 32; int i = ee / 3, k = ee % 3;
            for (int q = 0; q < 7; q++) v = fmaf(sh[8 + q], d_CG[OFF231 + (i * 7 + q) * 3 + k], v);
        } else if (j < 62) {
            int ee = j - 47; int i = ee / 5, k = ee % 5;
            for (int q = 0; q < 3; q++) v = fmaf(sh[q], d_CG[OFF112 + (i * 3 + q) * 5 + k], v);
        } else if (j < 77) {
            int ee = j - 62; int i = ee / 5, k = ee % 5;
            for (int q = 0; q < 7; q++) v = fmaf(sh[8 + q], d_CG[OFF132 + (i * 7 + q) * 5 + k], v);
        } else {
            int ee = j - 77; int i = ee / 5, k = ee % 5;
            for (int q = 0; q < 5; q++) v = fmaf(sh[3 + q], d_CG[OFF222 + (i * 5 + q) * 5 + k], v);
        }
        sT[e * 104 + j] = v;
    }
    __syncthreads();

    {
        float a0 = 0.f, a1 = 0.f, a2 = 0.f, a3 = 0.f;
#pragma unroll
        for (int i = 0; i < 8; i++) {
            float w = Wm1[i * 64 + ft];
            float4 r = *(const float4*)(sradT + i * 16 + 4 * g);
            a0 = fmaf(r.x, w, a0); a1 = fmaf(r.y, w, a1);
            a2 = fmaf(r.z, w, a2); a3 = fmaf(r.w, w, a3);
        }
        const float s8 = 0.35355339059327f;
        h1[ft * 20 + 4 * g + 0] = swishf(a0 * s8);
        h1[ft * 20 + 4 * g + 1] = swishf(a1 * s8);
        h1[ft * 20 + 4 * g + 2] = swishf(a2 * s8);
        h1[ft * 20 + 4 * g + 3] = swishf(a3 * s8);
    }
    __syncthreads();

    {
        float a0 = 0.f, a1 = 0.f, a2 = 0.f, a3 = 0.f;
#pragma unroll 8
        for (int f = 0; f < 64; f++) {
            float w = Wm2[f * 64 + ft];
            float4 hv = *(const float4*)(h1 + f * 20 + 4 * g);
            a0 = fmaf(hv.x, w, a0); a1 = fmaf(hv.y, w, a1);
            a2 = fmaf(hv.z, w, a2); a3 = fmaf(hv.w, w, a3);
        }
        const float s64 = 0.125f;
        h2[ft * 20 + 4 * g + 0] = swishf(a0 * s64);
        h2[ft * 20 + 4 * g + 1] = swishf(a1 * s64);
        h2[ft * 20 + 4 * g + 2] = swishf(a2 * s64);
        h2[ft * 20 + 4 * g + 3] = swishf(a3 * s64);
    }
    __syncthreads();

    const float msc = 0.125f * 0.316227766016838f;

    // PASS A: channels {0,1,3,4,5,9,10,11} (s0/s1)
    {
        float acc[8][4];
#pragma unroll
        for (int q = 0; q < 8; q++)
#pragma unroll
            for (int el = 0; el < 4; el++) acc[q][el] = 0.f;
#pragma unroll 2
        for (int f = 0; f < 64; f++) {
            float4 hv = *(const float4*)(h2 + f * 20 + 4 * g);
            const float* wrow = Wm3 + f * 832 + ft;
            float w;
#define FMA4(Q, M)                                            \
            w = wrow[(M) * 64];                               \
            acc[Q][0] = fmaf(hv.x, w, acc[Q][0]);             \
            acc[Q][1] = fmaf(hv.y, w, acc[Q][1]);             \
            acc[Q][2] = fmaf(hv.z, w, acc[Q][2]);             \
            acc[Q][3] = fmaf(hv.w, w, acc[Q][3]);
            FMA4(0, 0) FMA4(1, 1) FMA4(2, 3) FMA4(3, 4)
            FMA4(4, 5) FMA4(5, 9) FMA4(6, 10) FMA4(7, 11)
#undef FMA4
        }
#pragma unroll
        for (int q = 0; q < 8; q++)
#pragma unroll
            for (int el = 0; el < 4; el++) acc[q][el] *= msc;

#pragma unroll
        for (int el = 0; el < 4; el++) {
            int e = 4 * g + el;
            if (!sact[e]) continue;
            int sn = ssend[e];
            float* ap = abuf + (size_t)srecv[e] * 2752;
            const float* T = sT + e * 104;
            const float* sh = ssh + e * 16;
            float s0v = g0buf[sn * 64 + ft];
            float s1a = g1buf[sn * 192 + 0 * 64 + ft];
            float s1b = g1buf[sn * 192 + 1 * 64 + ft];
            float s1c = g1buf[sn * 192 + 2 * 64 + ft];

            atomicAdd(ap + ft, s0v * acc[0][el]);
            float tp110 = s1a * T[0] + s1b * T[1] + s1c * T[2];
            atomicAdd(ap + 64 + ft, tp110 * acc[1][el]);
#pragma unroll
            for (int c = 0; c < 3; c++) {
                float* p = ap + 192 + c * 320;
                float s1cc = (c == 0) ? s1a : ((c == 1) ? s1b : s1c);
                atomicAdd(p + ft, s1cc * acc[2][el]);
                atomicAdd(p + 64 + ft, s0v * sh[c] * acc[3][el]);
                float t121 = s1a * T[8 + c] + s1b * T[11 + c] + s1c * T[14 + c];
                atomicAdd(p + 128 + ft, t121 * acc[4][el]);
            }
#pragma unroll
            for (int c = 0; c < 5; c++) {
                float* p = ap + 1152 + c * 320;
                atomicAdd(p + 64 + ft, s0v * sh[3 + c] * acc[5][el]);
                float t112 = s1a * T[47 + c] + s1b * T[52 + c] + s1c * T[57 + c];
                atomicAdd(p + 128 + ft, t112 * acc[6][el]);
                float t132 = s1a * T[62 + c] + s1b * T[67 + c] + s1c * T[72 + c];
                atomicAdd(p + 192 + ft, t132 * acc[7][el]);
            }
        }
    }

    // PASS B: channels {2,6,7,8,12} (s2)
    {
        float acc[5][4];
#pragma unroll
        for (int q = 0; q < 5; q++)
#pragma unroll
            for (int el = 0; el < 4; el++) acc[q][el] = 0.f;
#pragma unroll 2
        for (int f = 0; f < 64; f++) {
            float4 hv = *(const float4*)(h2 + f * 20 + 4 * g);
            const float* wrow = Wm3 + f * 832 + ft;
            float w;
#define FMA4(Q, M)                                            \
            w = wrow[(M) * 64];                               \
            acc[Q][0] = fmaf(hv.x, w, acc[Q][0]);             \
            acc[Q][1] = fmaf(hv.y, w, acc[Q][1]);             \
            acc[Q][2] = fmaf(hv.z, w, acc[Q][2]);             \
            acc[Q][3] = fmaf(hv.w, w, acc[Q][3]);
            FMA4(0, 2) FMA4(1, 6) FMA4(2, 7) FMA4(3, 8) FMA4(4, 12)
#undef FMA4
        }
#pragma unroll
        for (int q = 0; q < 5; q++)
#pragma unroll
            for (int el = 0; el < 4; el++) acc[q][el] *= msc;

#pragma unroll
        for (int el = 0; el < 4; el++) {
            int e = 4 * g + el;
            if (!sact[e]) continue;
            int sn = ssend[e];
            float* ap = abuf + (size_t)srecv[e] * 2752;
            const float* T = sT + e * 104;
            float s2v[5];
#pragma unroll
            for (int c = 0; c < 5; c++) s2v[c] = g2buf[sn * 320 + c * 64 + ft];

            float tp220 = 0.f;
#pragma unroll
            for (int i = 0; i < 5; i++) tp220 = fmaf(s2v[i], T[3 + i], tp220);
            atomicAdd(ap + 128 + ft, tp220 * acc[0][el]);

#pragma unroll
            for (int c = 0; c < 3; c++) {
                float* p = ap + 192 + c * 320;
                float t211 = 0.f, t231 = 0.f;
#pragma unroll
                for (int i = 0; i < 5; i++) {
                    t211 = fmaf(s2v[i], T[17 + i * 3 + c], t211);
                    t231 = fmaf(s2v[i], T[32 + i * 3 + c], t231);
                }
                atomicAdd(p + 192 + ft, t211 * acc[1][el]);
                atomicAdd(p + 256 + ft, t231 * acc[2][el]);
            }
#pragma unroll
            for (int c = 0; c < 5; c++) {
                float* p = ap + 1152 + c * 320;
                atomicAdd(p + ft, s2v[c] * acc[3][el]);
                float t222 = 0.f;
#pragma unroll
                for (int i = 0; i < 5; i++) t222 = fmaf(s2v[i], T[77 + i * 5 + c], t222);
                atomicAdd(p + 256 + ft, t222 * acc[4][el]);
            }
        }
    }
}

// ---------------- node output: 4 nodes / block, 320 threads (round-7 proven version) ----------------
__global__ void __launch_bounds__(320) node_out_kernel(const float* __restrict__ Wd0,
                                const float* __restrict__ Wd1,
                                const float* __restrict__ Wd2,
                                float* __restrict__ out) {
    int n0 = blockIdx.x * 4;
    int t = threadIdx.x;
    __shared__ float saT[2752 * 4];
    __shared__ float sd0[4 * 192];

    for (int j = t; j < 2752; j += 320) {
#pragma unroll
        for (int nn = 0; nn < 4; nn++)
            saT[j * 4 + nn] = abuf[(size_t)(n0 + nn) * 2752 + j];
    }
    __syncthreads();

    if (t < 192) {
        float a0 = 0.f, a1 = 0.f, a2 = 0.f, a3 = 0.f;
#pragma unroll 8
        for (int m = 0; m < 192; m++) {
            float w = Wd0[m * 192 + t];
            float4 av = *(const float4*)(saT + m * 4);
            a0 = fmaf(av.x, w, a0); a1 = fmaf(av.y, w, a1);
            a2 = fmaf(av.z, w, a2); a3 = fmaf(av.w, w, a3);
        }
        const float s = 0.0721687836487032f;
        sd0[0 * 192 + t] = swishf(a0 * s);
        sd0[1 * 192 + t] = swishf(a1 * s);
        sd0[2 * 192 + t] = swishf(a2 * s);
        sd0[3 * 192 + t] = swishf(a3 * s);
    }
    __syncthreads();

    if (t < 64) {
#pragma unroll
        for (int nn = 0; nn < 4; nn++)
            out[(size_t)(n0 + nn) * 576 + t] += sd0[nn * 192 + t];
    }

    const float s320 = 0.0559016994374947f;

    if (t < 192) {
        int c = t / 64, f = t % 64;
        float a0 = 0.f, a1 = 0.f, a2 = 0.f, a3 = 0.f;
        const float* base = saT + (192 + c * 320) * 4;
#pragma unroll 8
        for (int m = 0; m < 320; m++) {
            float w = Wd1[m * 64 + f];
            float4 av = *(const float4*)(base + m * 4);
            a0 = fmaf(av.x, w, a0); a1 = fmaf(av.y, w, a1);
            a2 = fmaf(av.z, w, a2); a3 = fmaf(av.w, w, a3);
        }
        float r[4] = {a0, a1, a2, a3};
#pragma unroll
        for (int nn = 0; nn < 4; nn++)
            out[(size_t)(n0 + nn) * 576 + 64 + f * 3 + c] += r[nn] * s320 * sd0[nn * 192 + 64 + f];
    }

    {
        int c = t / 64, f = t % 64;
        float a0 = 0.f, a1 = 0.f, a2 = 0.f, a3 = 0.f;
        const float* base = saT + (1152 + c * 320) * 4;
#pragma unroll 8
        for (int m = 0; m < 320; m++) {
            float w = Wd2[m * 64 + f];
            float4 av = *(const float4*)(base + m * 4);
            a0 = fmaf(av.x, w, a0); a1 = fmaf(av.y, w, a1);
            a2 = fmaf(av.z, w, a2); a3 = fmaf(av.w, w, a3);
        }
        float r[4] = {a0, a1, a2, a3};
#pragma unroll
        for (int nn = 0; nn < 4; nn++)
            out[(size_t)(n0 + nn) * 576 + 256 + f * 5 + c] += r[nn] * s320 * sd0[nn * 192 + 128 + f];
    }
}

// ---------------- launcher ----------------
extern "C" void kernel_launch(void* const* d_in, const int* in_sizes, int n_in,
                              void* d_out, int out_size) {
    const float* vectors    = (const float*)d_in[0];
    const float* node_feats = (const float*)d_in[1];
    const int*   node_specie= (const int*)d_in[2];
    const int*   senders    = (const int*)d_in[3];
    const int*   receivers  = (const int*)d_in[4];
    const float* Wsc0 = (const float*)d_in[5];
    const float* Wsc1 = (const float*)d_in[6];
    const float* Wsc2 = (const float*)d_in[7];
    const float* Wu0  = (const float*)d_in[8];
    const float* Wu1  = (const float*)d_in[9];
    const float* Wu2  = (const float*)d_in[10];
    const float* Wm1  = (const float*)d_in[11];
    const float* Wm2  = (const float*)d_in[12];
    const float* Wm3  = (const float*)d_in[13];
    const float* Wd0  = (const float*)d_in[14];
    const float* Wd1  = (const float*)d_in[15];
    const float* Wd2  = (const float*)d_in[16];
    float* out = (float*)d_out;

    fused_prep_kernel<<<FUSED_BLOCKS, 256>>>(node_feats, node_specie,
                                             Wsc0, Wsc1, Wsc2, Wu0, Wu1, Wu2, out);
    edge_kernel<<<NEDGE / 16, 256>>>(vectors, senders, receivers, Wm1, Wm2, Wm3);
    node_out_kernel<<<NNODE / 4, 320>>>(Wd0, Wd1, Wd2, out);
}

// round 15
// speedup vs baseline: 1.0589x; 1.0115x over previous
#include <cuda_runtime.h>
#include <cuda_bf16.h>
#include <math.h>

#define NNODE 5000
#define NEDGE 50000
#define FDIM 64

// ---------------- device scratch ----------------
__device__ float g0buf[NNODE * 64];
__device__ float g1buf[NNODE * 192];   // [n][c(3)][f(64)]
__device__ float g2buf[NNODE * 320];   // [n][c(5)][f(64)]
__device__ float abuf[NNODE * 2752];   // [n][ a0(192) | a1(960) | a2(1600) ]
__device__ float d_CG[504];
// interleaved decoder weights: [(mo*COLS + col)*4 + fi] = W[(4*mo+fi)*COLS + col]
__device__ float wd0t[48 * 192 * 4];
__device__ float wd1t[80 * 64 * 4];
__device__ float wd2t[80 * 64 * 4];

#define OFF110 0
#define OFF220 9
#define OFF121 34
#define OFF211 79
#define OFF231 124
#define OFF112 229
#define OFF132 274
#define OFF222 379

// factorials and inverses (exact in fp64 for n<=9)
__constant__ double c_F[10]   = {1., 1., 2., 6., 24., 120., 720., 5040., 40320., 362880.};
__constant__ double c_INV[10] = {1., 1., 1.0/2., 1.0/6., 1.0/24., 1.0/120., 1.0/720.,
                                 1.0/5040., 1.0/40320., 1.0/362880.};

__device__ double cgc_fast(int j1, int m1, int j2, int m2, int j3, int m3) {
    if (m1 + m2 != m3) return 0.0;
    int lo = j1 - j2; if (lo < 0) lo = -lo;
    if (j3 < lo || j3 > j1 + j2) return 0.0;
    double pref = sqrt((2.0 * j3 + 1.0) * c_F[j3 + j1 - j2] * c_F[j3 - j1 + j2] *
                       c_F[j1 + j2 - j3] * c_INV[j1 + j2 + j3 + 1]);
    pref *= sqrt(c_F[j3 + m3] * c_F[j3 - m3] * c_F[j1 - m1] * c_F[j1 + m1] *
                 c_F[j2 - m2] * c_F[j2 + m2]);
    double s = 0.0;
    for (int k = 0; k <= j1 + j2 + j3; k++) {
        int d0 = j1 + j2 - j3 - k, d1 = j1 - m1 - k, d2 = j2 + m2 - k;
        int d3 = j3 - j2 + m1 + k, d4 = j3 - j1 - m2 + k;
        if (d0 < 0 || d1 < 0 || d2 < 0 || d3 < 0 || d4 < 0) continue;
        double term = c_INV[k] * c_INV[d0] * c_INV[d1] * c_INV[d2] * c_INV[d3] * c_INV[d4];
        s += (k & 1) ? -term : term;
    }
    return pref * s;
}

__device__ double2 Umat(int l, int i, int a) {
    const double s = 0.70710678118654752440;
    int mi = i - l;
    if (mi == 0) return (a == l) ? make_double2(1.0, 0.0) : make_double2(0.0, 0.0);
    if (mi > 0) {
        int m = mi; double sgn = (m & 1) ? -1.0 : 1.0;
        if (a == l + m) return make_double2(sgn * s, 0.0);
        if (a == l - m) return make_double2(s, 0.0);
    } else {
        int m = -mi; double sgn = (m & 1) ? -1.0 : 1.0;
        if (a == l - m) return make_double2(0.0, s);
        if (a == l + m) return make_double2(0.0, -sgn * s);
    }
    return make_double2(0.0, 0.0);
}

__device__ __forceinline__ float swishf(float x) {
    return x / (1.0f + __expf(-x));
}

// ---------------- fused: CG init + zero accumulators + weight transpose + node_prep ----------------
#define FUSED_BLOCKS 2048
#define PREP_FIRST 63
#define PREP_COUNT 1250

__global__ void __launch_bounds__(256) fused_prep_kernel(
        const float* __restrict__ nf,
        const int* __restrict__ specie,
        const float* __restrict__ Wsc0, const float* __restrict__ Wsc1,
        const float* __restrict__ Wsc2, const float* __restrict__ Wu0,
        const float* __restrict__ Wu1, const float* __restrict__ Wu2,
        const float* __restrict__ Wd0, const float* __restrict__ Wd1,
        const float* __restrict__ Wd2,
        float* __restrict__ out) {
    int b = blockIdx.x;
    int t = threadIdx.x;

    if (b >= PREP_FIRST && b < PREP_FIRST + PREP_COUNT) {
        // ---------- node_prep: 4 nodes per block ----------
        __shared__ float sf[4 * 576];
        int nb = (b - PREP_FIRST) * 4;
        {
            const float4* src = (const float4*)(nf + (size_t)nb * 576);
            float4* dst = (float4*)sf;
            for (int i = t; i < 576; i += 256) dst[i] = src[i];
        }
        __syncthreads();

        int g = t & 63;
        int ln = t >> 6;
        int n = nb + ln;
        const float* sfp = sf + ln * 576;
        int sp = specie[n];
        const float* w0p = Wsc0 + sp * 4096;
        const float* w1p = Wsc1 + sp * 4096;
        const float* w2p = Wsc2 + sp * 4096;

        float sc0 = 0.f, g0 = 0.f;
        float sc1[3] = {0.f, 0.f, 0.f}, g1[3] = {0.f, 0.f, 0.f};
        float sc2[5] = {0.f, 0.f, 0.f, 0.f, 0.f}, g2[5] = {0.f, 0.f, 0.f, 0.f, 0.f};
#pragma unroll 4
        for (int f = 0; f < 64; f++) {
            float w0 = w0p[f * 64 + g], u0 = Wu0[f * 64 + g];
            float w1 = w1p[f * 64 + g], u1 = Wu1[f * 64 + g];
            float w2 = w2p[f * 64 + g], u2 = Wu2[f * 64 + g];
            float v0 = sfp[f];
            sc0 = fmaf(v0, w0, sc0);
            g0  = fmaf(v0, u0, g0);
#pragma unroll
            for (int c = 0; c < 3; c++) {
                float v = sfp[64 + f * 3 + c];
                sc1[c] = fmaf(v, w1, sc1[c]);
                g1[c]  = fmaf(v, u1, g1[c]);
            }
#pragma unroll
            for (int c = 0; c < 5; c++) {
                float v = sfp[256 + f * 5 + c];
                sc2[c] = fmaf(v, w2, sc2[c]);
                g2[c]  = fmaf(v, u2, g2[c]);
            }
        }
        const float invF = 0.125f;
        float* orow = out + (size_t)n * 576;
        orow[g] = sc0 * invF;
#pragma unroll
        for (int c = 0; c < 3; c++) orow[64 + g * 3 + c] = sc1[c] * invF;
#pragma unroll
        for (int c = 0; c < 5; c++) orow[256 + g * 5 + c] = sc2[c] * invF;
        g0buf[n * 64 + g] = g0 * invF;
#pragma unroll
        for (int c = 0; c < 3; c++) g1buf[n * 192 + c * 64 + g] = g1[c] * invF;
#pragma unroll
        for (int c = 0; c < 5; c++) g2buf[n * 320 + c * 64 + g] = g2[c] * invF;
        return;
    }

    // ---------- CG (blocks 0..62) ----------
    if (b < PREP_FIRST) {
        int warp_gid = b * 8 + (t >> 5);
        int lane = t & 31;
        if (warp_gid < 504) {
            int idx = warp_gid;
            int l1, l2, l3, flat;
            if (idx < 9)        { l1 = 1; l2 = 1; l3 = 0; flat = idx; }
            else if (idx < 34)  { l1 = 2; l2 = 2; l3 = 0; flat = idx - 9; }
            else if (idx < 79)  { l1 = 1; l2 = 2; l3 = 1; flat = idx - 34; }
            else if (idx < 124) { l1 = 2; l2 = 1; l3 = 1; flat = idx - 79; }
            else if (idx < 229) { l1 = 2; l2 = 3; l3 = 1; flat = idx - 124; }
            else if (idx < 274) { l1 = 1; l2 = 1; l3 = 2; flat = idx - 229; }
            else if (idx < 379) { l1 = 1; l2 = 3; l3 = 2; flat = idx - 274; }
            else                { l1 = 2; l2 = 2; l3 = 2; flat = idx - 379; }
            int dd2 = 2 * l2 + 1, dd3 = 2 * l3 + 1;
            int i = flat / (dd2 * dd3), j = (flat / dd3) % dd2, k = flat % dd3;

            int d1 = 2 * l1 + 1, d2 = 2 * l2 + 1, d3 = 2 * l3 + 1;
            double re = 0.0;
            for (int ab = lane; ab < d1 * d2; ab += 32) {
                int a = ab / d2, bb = ab % d2;
                double2 u1 = Umat(l1, i, a);
                if (u1.x == 0.0 && u1.y == 0.0) continue;
                double2 u2 = Umat(l2, j, bb);
                if (u2.x == 0.0 && u2.y == 0.0) continue;
                double pr = u1.x * u2.x - u1.y * u2.y;
                double pi = u1.x * u2.y + u1.y * u2.x;
                for (int c = 0; c < d3; c++) {
                    double2 u3 = Umat(l3, k, c);
                    u3.y = -u3.y;
                    if (u3.x == 0.0 && u3.y == 0.0) continue;
                    double cg = cgc_fast(l1, a - l1, l2, bb - l2, l3, c - l3);
                    if (cg == 0.0) continue;
                    re += (pr * u3.x - pi * u3.y) * cg;
                }
            }
            __syncwarp();
#pragma unroll
            for (int off = 16; off > 0; off >>= 1)
                re += __shfl_xor_sync(0xffffffffu, re, off);
            if (lane == 0) d_CG[idx] = (float)re;
        }
    }

    // ---------- zero accumulators + weight transpose (blocks 0..62 and 1313..2047) ----------
    int zrank = (b < PREP_FIRST) ? b : (b - PREP_COUNT);
    int zcount = FUSED_BLOCKS - PREP_COUNT;  // 798
    int gid = zrank * 256 + t;
    int stride = zcount * 256;

    // decoder weight interleave
    for (int q = gid; q < 36864; q += stride) {
        int fi = q & 3, tt = (q >> 2) % 192, mo = (q >> 2) / 192;
        wd0t[q] = Wd0[(4 * mo + fi) * 192 + tt];
    }
    for (int q = gid; q < 20480; q += stride) {
        int fi = q & 3, f = (q >> 2) & 63, mo = q >> 8;
        wd1t[q] = Wd1[(4 * mo + fi) * 64 + f];
        wd2t[q] = Wd2[(4 * mo + fi) * 64 + f];
    }

    float4* p = reinterpret_cast<float4*>(abuf);
    int n4 = NNODE * 2752 / 4;
    float4 z = make_float4(0.f, 0.f, 0.f, 0.f);
    for (int q = gid; q < n4; q += stride) p[q] = z;
}

// ---------------- edge kernel (round-7 proven version) ----------------
__global__ void __launch_bounds__(256, 4) edge_kernel(const float* __restrict__ vectors,
                            const int* __restrict__ senders,
                            const int* __restrict__ receivers,
                            const float* __restrict__ Wm1,
                            const float* __restrict__ Wm2,
                            const float* __restrict__ Wm3) {
    __shared__ float h1[64 * 20];
    __shared__ float h2[64 * 20];
    __shared__ float sT[16 * 104];
    __shared__ float ssh[16 * 16];
    __shared__ float sradT[8 * 16];
    __shared__ float sx[16], sinvx[16];
    __shared__ int ssend[16], srecv[16], sact[16];

    int t = threadIdx.x;
    int ft = t & 63;
    int g = t >> 6;
    int e0 = blockIdx.x * 16;

    if (t < 16) {
        int e = e0 + t;
        float vx = vectors[e * 3 + 0], vy = vectors[e * 3 + 1], vz = vectors[e * 3 + 2];
        float x = sqrtf(fmaxf(vx * vx + vy * vy + vz * vz, 1e-12f));
        float invx = 1.0f / x;
        float ux = vx * invx, uy = vy * invx, uz = vz * invx;
        sx[t] = x; sinvx[t] = invx;
        sact[t] = (x < 1.0f) ? 1 : 0;
        ssend[t] = senders[e];
        srecv[t] = receivers[e];
        float* sh = ssh + t * 16;
        const float s3 = 1.7320508075688772f;
        const float s15 = 3.872983346207417f;
        const float s5 = 2.23606797749979f;
        const float c35 = 2.091650066335189f;
        const float c105 = 10.246950765959598f;
        const float c21 = 1.6201851746019651f;
        const float c7 = 1.3228756555322954f;
        sh[0] = s3 * uy; sh[1] = s3 * uz; sh[2] = s3 * ux;
        sh[3] = s15 * ux * uy;
        sh[4] = s15 * uy * uz;
        sh[5] = 0.5f * s5 * (3.0f * uz * uz - 1.0f);
        sh[6] = s15 * ux * uz;
        sh[7] = 0.5f * s15 * (ux * ux - uy * uy);
        sh[8]  = c35 * uy * (3.0f * ux * ux - uy * uy);
        sh[9]  = c105 * ux * uy * uz;
        sh[10] = c21 * uy * (5.0f * uz * uz - 1.0f);
        sh[11] = c7 * uz * (5.0f * uz * uz - 3.0f);
        sh[12] = c21 * ux * (5.0f * uz * uz - 1.0f);
        sh[13] = 0.5f * c105 * uz * (ux * ux - uy * uy);
        sh[14] = c35 * ux * (ux * ux - 3.0f * uy * uy);
        sh[15] = 0.f;
    }
    __syncthreads();

    if (t < 128) {
        int e = t & 15, n = t >> 4;
        float x = sx[e];
        float env = 0.f;
        if (x < 1.0f) {
            float x2 = x * x, x4 = x2 * x2, x6 = x4 * x2, x7 = x6 * x, x8 = x7 * x;
            env = 1.0f - 28.0f * x6 + 48.0f * x7 - 21.0f * x8;
        }
        float nn = (float)(n + 1);
        sradT[n * 16 + e] = 1.41421356237f * sinf(3.14159265358979f * nn * x) * sinvx[e] * env;
    }
    __syncthreads();

    for (int idx = t; idx < 16 * 102; idx += 256) {
        int e = idx / 102, j = idx % 102;
        const float* sh = ssh + e * 16;
        float v = 0.f;
        if (j < 3) {
            int i = j;
            for (int q = 0; q < 3; q++) v = fmaf(sh[q], d_CG[OFF110 + i * 3 + q], v);
        } else if (j < 8) {
            int i = j - 3;
            for (int q = 0; q < 5; q++) v = fmaf(sh[3 + q], d_CG[OFF220 + i * 5 + q], v);
        } else if (j < 17) {
            int ee = j - 8; int i = ee / 3, k = ee % 3;
            for (int q = 0; q < 5; q++) v = fmaf(sh[3 + q], d_CG[OFF121 + (i * 5 + q) * 3 + k], v);
        } else if (j < 32) {
            int ee = j - 17; int i = ee / 3, k = ee % 3;
            for (int q = 0; q < 3; q++) v = fmaf(sh[q], d_CG[OFF211 + (i * 3 + q) * 3 + k], v);
        } else if (j < 47) {
            int ee = j - 32; int i = ee / 3, k = ee % 3;
            for (int q = 0; q < 7; q++) v = fmaf(sh[8 + q], d_CG[OFF231 + (i * 7 + q) * 3 + k], v);
        } else if (j < 62) {
            int ee = j - 47; int i = ee / 5, k = ee % 5;
            for (int q = 0; q < 3; q++) v = fmaf(sh[q], d_CG[OFF112 + (i * 3 + q) * 5 + k], v);
        } else if (j < 77) {
            int ee = j - 62; int i = ee / 5, k = ee % 5;
            for (int q = 0; q < 7; q++) v = fmaf(sh[8 + q], d_CG[OFF132 + (i * 7 + q) * 5 + k], v);
        } else {
            int ee = j - 77; int i = ee / 5, k = ee % 5;
            for (int q = 0; q < 5; q++) v = fmaf(sh[3 + q], d_CG[OFF222 + (i * 5 + q) * 5 + k], v);
        }
        sT[e * 104 + j] = v;
    }
    __syncthreads();

    {
        float a0 = 0.f, a1 = 0.f, a2 = 0.f, a3 = 0.f;
#pragma unroll
        for (int i = 0; i < 8; i++) {
            float w = Wm1[i * 64 + ft];
            float4 r = *(const float4*)(sradT + i * 16 + 4 * g);
            a0 = fmaf(r.x, w, a0); a1 = fmaf(r.y, w, a1);
            a2 = fmaf(r.z, w, a2); a3 = fmaf(r.w, w, a3);
        }
        const float s8 = 0.35355339059327f;
        h1[ft * 20 + 4 * g + 0] = swishf(a0 * s8);
        h1[ft * 20 + 4 * g + 1] = swishf(a1 * s8);
        h1[ft * 20 + 4 * g + 2] = swishf(a2 * s8);
        h1[ft * 20 + 4 * g + 3] = swishf(a3 * s8);
    }
    __syncthreads();

    {
        float a0 = 0.f, a1 = 0.f, a2 = 0.f, a3 = 0.f;
#pragma unroll 8
        for (int f = 0; f < 64; f++) {
            float w = Wm2[f * 64 + ft];
            float4 hv = *(const float4*)(h1 + f * 20 + 4 * g);
            a0 = fmaf(hv.x, w, a0); a1 = fmaf(hv.y, w, a1);
            a2 = fmaf(hv.z, w, a2); a3 = fmaf(hv.w, w, a3);
        }
        const float s64 = 0.125f;
        h2[ft * 20 + 4 * g + 0] = swishf(a0 * s64);
        h2[ft * 20 + 4 * g + 1] = swishf(a1 * s64);
        h2[ft * 20 + 4 * g + 2] = swishf(a2 * s64);
        h2[ft * 20 + 4 * g + 3] = swishf(a3 * s64);
    }
    __syncthreads();

    const float msc = 0.125f * 0.316227766016838f;

    // PASS A: channels {0,1,3,4,5,9,10,11} (s0/s1)
    {
        float acc[8][4];
#pragma unroll
        for (int q = 0; q < 8; q++)
#pragma unroll
            for (int el = 0; el < 4; el++) acc[q][el] = 0.f;
#pragma unroll 2
        for (int f = 0; f < 64; f++) {
            float4 hv = *(const float4*)(h2 + f * 20 + 4 * g);
            const float* wrow = Wm3 + f * 832 + ft;
            float w;
#define FMA4(Q, M)                                            \
            w = wrow[(M) * 64];                               \
            acc[Q][0] = fmaf(hv.x, w, acc[Q][0]);             \
            acc[Q][1] = fmaf(hv.y, w, acc[Q][1]);             \
            acc[Q][2] = fmaf(hv.z, w, acc[Q][2]);             \
            acc[Q][3] = fmaf(hv.w, w, acc[Q][3]);
            FMA4(0, 0) FMA4(1, 1) FMA4(2, 3) FMA4(3, 4)
            FMA4(4, 5) FMA4(5, 9) FMA4(6, 10) FMA4(7, 11)
#undef FMA4
        }
#pragma unroll
        for (int q = 0; q < 8; q++)
#pragma unroll
            for (int el = 0; el < 4; el++) acc[q][el] *= msc;

#pragma unroll
        for (int el = 0; el < 4; el++) {
            int e = 4 * g + el;
            if (!sact[e]) continue;
            int sn = ssend[e];
            float* ap = abuf + (size_t)srecv[e] * 2752;
            const float* T = sT + e * 104;
            const float* sh = ssh + e * 16;
            float s0v = g0buf[sn * 64 + ft];
            float s1a = g1buf[sn * 192 + 0 * 64 + ft];
            float s1b = g1buf[sn * 192 + 1 * 64 + ft];
            float s1c = g1buf[sn * 192 + 2 * 64 + ft];

            atomicAdd(ap + ft, s0v * acc[0][el]);
            float tp110 = s1a * T[0] + s1b * T[1] + s1c * T[2];
            atomicAdd(ap + 64 + ft, tp110 * acc[1][el]);
#pragma unroll
            for (int c = 0; c < 3; c++) {
                float* p = ap + 192 + c * 320;
                float s1cc = (c == 0) ? s1a : ((c == 1) ? s1b : s1c);
                atomicAdd(p + ft, s1cc * acc[2][el]);
                atomicAdd(p + 64 + ft, s0v * sh[c] * acc[3][el]);
                float t121 = s1a * T[8 + c] + s1b * T[11 + c] + s1c * T[14 + c];
                atomicAdd(p + 128 + ft, t121 * acc[4][el]);
            }
#pragma unroll
            for (int c = 0; c < 5; c++) {
                float* p = ap + 1152 + c * 320;
                atomicAdd(p + 64 + ft, s0v * sh[3 + c] * acc[5][el]);
                float t112 = s1a * T[47 + c] + s1b * T[52 + c] + s1c * T[57 + c];
                atomicAdd(p + 128 + ft, t112 * acc[6][el]);
                float t132 = s1a * T[62 + c] + s1b * T[67 + c] + s1c * T[72 + c];
                atomicAdd(p + 192 + ft, t132 * acc[7][el]);
            }
        }
    }

    // PASS B: channels {2,6,7,8,12} (s2)
    {
        float acc[5][4];
#pragma unroll
        for (int q = 0; q < 5; q++)
#pragma unroll
            for (int el = 0; el < 4; el++) acc[q][el] = 0.f;
#pragma unroll 2
        for (int f = 0; f < 64; f++) {
            float4 hv = *(const float4*)(h2 + f * 20 + 4 * g);
            const float* wrow = Wm3 + f * 832 + ft;
            float w;
#define FMA4(Q, M)                                            \
            w = wrow[(M) * 64];                               \
            acc[Q][0] = fmaf(hv.x, w, acc[Q][0]);             \
            acc[Q][1] = fmaf(hv.y, w, acc[Q][1]);             \
            acc[Q][2] = fmaf(hv.z, w, acc[Q][2]);             \
            acc[Q][3] = fmaf(hv.w, w, acc[Q][3]);
            FMA4(0, 2) FMA4(1, 6) FMA4(2, 7) FMA4(3, 8) FMA4(4, 12)
#undef FMA4
        }
#pragma unroll
        for (int q = 0; q < 5; q++)
#pragma unroll
            for (int el = 0; el < 4; el++) acc[q][el] *= msc;

#pragma unroll
        for (int el = 0; el < 4; el++) {
            int e = 4 * g + el;
            if (!sact[e]) continue;
            int sn = ssend[e];
            float* ap = abuf + (size_t)srecv[e] * 2752;
            const float* T = sT + e * 104;
            float s2v[5];
#pragma unroll
            for (int c = 0; c < 5; c++) s2v[c] = g2buf[sn * 320 + c * 64 + ft];

            float tp220 = 0.f;
#pragma unroll
            for (int i = 0; i < 5; i++) tp220 = fmaf(s2v[i], T[3 + i], tp220);
            atomicAdd(ap + 128 + ft, tp220 * acc[0][el]);

#pragma unroll
            for (int c = 0; c < 3; c++) {
                float* p = ap + 192 + c * 320;
                float t211 = 0.f, t231 = 0.f;
#pragma unroll
                for (int i = 0; i < 5; i++) {
                    t211 = fmaf(s2v[i], T[17 + i * 3 + c], t211);
                    t231 = fmaf(s2v[i], T[32 + i * 3 + c], t231);
                }
                atomicAdd(p + 192 + ft, t211 * acc[1][el]);
                atomicAdd(p + 256 + ft, t231 * acc[2][el]);
            }
#pragma unroll
            for (int c = 0; c < 5; c++) {
                float* p = ap + 1152 + c * 320;
                atomicAdd(p + ft, s2v[c] * acc[3][el]);
                float t222 = 0.f;
#pragma unroll
                for (int i = 0; i < 5; i++) t222 = fmaf(s2v[i], T[77 + i * 5 + c], t222);
                atomicAdd(p + 256 + ft, t222 * acc[4][el]);
            }
        }
    }
}

// ---------------- node output v3: 4 nodes / block, vectorized weight loads ----------------
__global__ void __launch_bounds__(320) node_out_kernel(float* __restrict__ out) {
    int n0 = blockIdx.x * 4;
    int t = threadIdx.x;
    __shared__ float saT[2752 * 4];
    __shared__ float sd0[4 * 192];

    for (int j = t; j < 2752; j += 320) {
#pragma unroll
        for (int nn = 0; nn < 4; nn++)
            saT[j * 4 + nn] = abuf[(size_t)(n0 + nn) * 2752 + j];
    }
    __syncthreads();

    // d0: 48 chunks of 4 m, one LDG.128 per chunk
    if (t < 192) {
        float a0 = 0.f, a1 = 0.f, a2 = 0.f, a3 = 0.f;
        const float4* wb = ((const float4*)wd0t) + t;
#pragma unroll 4
        for (int mo = 0; mo < 48; mo++) {
            float4 w4 = wb[mo * 192];
            const float* base = saT + mo * 16;
            float4 v0 = *(const float4*)(base);
            float4 v1 = *(const float4*)(base + 4);
            float4 v2 = *(const float4*)(base + 8);
            float4 v3 = *(const float4*)(base + 12);
            a0 = fmaf(v0.x, w4.x, a0); a1 = fmaf(v0.y, w4.x, a1);
            a2 = fmaf(v0.z, w4.x, a2); a3 = fmaf(v0.w, w4.x, a3);
            a0 = fmaf(v1.x, w4.y, a0); a1 = fmaf(v1.y, w4.y, a1);
            a2 = fmaf(v1.z, w4.y, a2); a3 = fmaf(v1.w, w4.y, a3);
            a0 = fmaf(v2.x, w4.z, a0); a1 = fmaf(v2.y, w4.z, a1);
            a2 = fmaf(v2.z, w4.z, a2); a3 = fmaf(v2.w, w4.z, a3);
            a0 = fmaf(v3.x, w4.w, a0); a1 = fmaf(v3.y, w4.w, a1);
            a2 = fmaf(v3.z, w4.w, a2); a3 = fmaf(v3.w, w4.w, a3);
        }
        const float s = 0.0721687836487032f;  // 1/sqrt(192)
        sd0[0 * 192 + t] = swishf(a0 * s);
        sd0[1 * 192 + t] = swishf(a1 * s);
        sd0[2 * 192 + t] = swishf(a2 * s);
        sd0[3 * 192 + t] = swishf(a3 * s);
    }
    __syncthreads();

    if (t < 64) {
#pragma unroll
        for (int nn = 0; nn < 4; nn++)
            out[(size_t)(n0 + nn) * 576 + t] += sd0[nn * 192 + t];
    }

    const float s320 = 0.0559016994374947f;  // 1/sqrt(320)

    // d1: 80 chunks of 4 m
    if (t < 192) {
        int c = t / 64, f = t % 64;
        float a0 = 0.f, a1 = 0.f, a2 = 0.f, a3 = 0.f;
        const float4* wb = ((const float4*)wd1t) + f;
        const float* sbase = saT + (192 + c * 320) * 4;
#pragma unroll 4
        for (int mo = 0; mo < 80; mo++) {
            float4 w4 = wb[mo * 64];
            const float* base = sbase + mo * 16;
            float4 v0 = *(const float4*)(base);
            float4 v1 = *(const float4*)(base + 4);
            float4 v2 = *(const float4*)(base + 8);
            float4 v3 = *(const float4*)(base + 12);
            a0 = fmaf(v0.x, w4.x, a0); a1 = fmaf(v0.y, w4.x, a1);
            a2 = fmaf(v0.z, w4.x, a2); a3 = fmaf(v0.w, w4.x, a3);
            a0 = fmaf(v1.x, w4.y, a0); a1 = fmaf(v1.y, w4.y, a1);
            a2 = fmaf(v1.z, w4.y, a2); a3 = fmaf(v1.w, w4.y, a3);
            a0 = fmaf(v2.x, w4.z, a0); a1 = fmaf(v2.y, w4.z, a1);
            a2 = fmaf(v2.z, w4.z, a2); a3 = fmaf(v2.w, w4.z, a3);
            a0 = fmaf(v3.x, w4.w, a0); a1 = fmaf(v3.y, w4.w, a1);
            a2 = fmaf(v3.z, w4.w, a2); a3 = fmaf(v3.w, w4.w, a3);
        }
        float r[4] = {a0, a1, a2, a3};
#pragma unroll
        for (int nn = 0; nn < 4; nn++)
            out[(size_t)(n0 + nn) * 576 + 64 + f * 3 + c] += r[nn] * s320 * sd0[nn * 192 + 64 + f];
    }

    // d2: 80 chunks of 4 m, all 320 threads
    {
        int c = t / 64, f = t % 64;
        float a0 = 0.f, a1 = 0.f, a2 = 0.f, a3 = 0.f;
        const float4* wb = ((const float4*)wd2t) + f;
        const float* sbase = saT + (1152 + c * 320) * 4;
#pragma unroll 4
        for (int mo = 0; mo < 80; mo++) {
            float4 w4 = wb[mo * 64];
            const float* base = sbase + mo * 16;
            float4 v0 = *(const float4*)(base);
            float4 v1 = *(const float4*)(base + 4);
            float4 v2 = *(const float4*)(base + 8);
            float4 v3 = *(const float4*)(base + 12);
            a0 = fmaf(v0.x, w4.x, a0); a1 = fmaf(v0.y, w4.x, a1);
            a2 = fmaf(v0.z, w4.x, a2); a3 = fmaf(v0.w, w4.x, a3);
            a0 = fmaf(v1.x, w4.y, a0); a1 = fmaf(v1.y, w4.y, a1);
            a2 = fmaf(v1.z, w4.y, a2); a3 = fmaf(v1.w, w4.y, a3);
            a0 = fmaf(v2.x, w4.z, a0); a1 = fmaf(v2.y, w4.z, a1);
            a2 = fmaf(v2.z, w4.z, a2); a3 = fmaf(v2.w, w4.z, a3);
            a0 = fmaf(v3.x, w4.w, a0); a1 = fmaf(v3.y, w4.w, a1);
            a2 = fmaf(v3.z, w4.w, a2); a3 = fmaf(v3.w, w4.w, a3);
        }
        float r[4] = {a0, a1, a2, a3};
#pragma unroll
        for (int nn = 0; nn < 4; nn++)
            out[(size_t)(n0 + nn) * 576 + 256 + f * 5 + c] += r[nn] * s320 * sd0[nn * 192 + 128 + f];
    }
}

// ---------------- launcher ----------------
extern "C" void kernel_launch(void* const* d_in, const int* in_sizes, int n_in,
                              void* d_out, int out_size) {
    const float* vectors    = (const float*)d_in[0];
    const float* node_feats = (const float*)d_in[1];
    const int*   node_specie= (const int*)d_in[2];
    const int*   senders    = (const int*)d_in[3];
    const int*   receivers  = (const int*)d_in[4];
    const float* Wsc0 = (const float*)d_in[5];
    const float* Wsc1 = (const float*)d_in[6];
    const float* Wsc2 = (const float*)d_in[7];
    const float* Wu0  = (const float*)d_in[8];
    const float* Wu1  = (const float*)d_in[9];
    const float* Wu2  = (const float*)d_in[10];
    const float* Wm1  = (const float*)d_in[11];
    const float* Wm2  = (const float*)d_in[12];
    const float* Wm3  = (const float*)d_in[13];
    const float* Wd0  = (const float*)d_in[14];
    const float* Wd1  = (const float*)d_in[15];
    const float* Wd2  = (const float*)d_in[16];
    float* out = (float*)d_out;

    fused_prep_kernel<<<FUSED_BLOCKS, 256>>>(node_feats, node_specie,
                                             Wsc0, Wsc1, Wsc2, Wu0, Wu1, Wu2,
                                             Wd0, Wd1, Wd2, out);
    edge_kernel<<<NEDGE / 16, 256>>>(vectors, senders, receivers, Wm1, Wm2, Wm3);
    node_out_kernel<<<NNODE / 4, 320>>>(out);
}

// round 16
// speedup vs baseline: 1.1387x; 1.0753x over previous
#include <cuda_runtime.h>
#include <cuda_bf16.h>
#include <math.h>

#define NNODE 5000
#define NEDGE 50000
#define FDIM 64

// ---------------- device scratch ----------------
__device__ float g0buf[NNODE * 64];
__device__ float g1buf[NNODE * 192];   // [n][c(3)][f(64)]
__device__ float g2buf[NNODE * 320];   // [n][c(5)][f(64)]
__device__ float abuf[NNODE * 2752];   // [n][ a0(192) | a1(960) | a2(1600) ]
__device__ float d_CG[504];
// interleaved decoder weights: [(mo*COLS + col)*4 + fi] = W[(4*mo+fi)*COLS + col]
__device__ float wd0t[48 * 192 * 4];
__device__ float wd1t[80 * 64 * 4];
__device__ float wd2t[80 * 64 * 4];
// interleaved Wm3: [((ch*32 + fo)*64 + ft)*2 + fi] = Wm3[(2*fo+fi)*832 + ch*64 + ft]
__device__ float wm3t[13 * 32 * 64 * 2];

#define OFF110 0
#define OFF220 9
#define OFF121 34
#define OFF211 79
#define OFF231 124
#define OFF112 229
#define OFF132 274
#define OFF222 379

// factorials and inverses (exact in fp64 for n<=9)
__constant__ double c_F[10]   = {1., 1., 2., 6., 24., 120., 720., 5040., 40320., 362880.};
__constant__ double c_INV[10] = {1., 1., 1.0/2., 1.0/6., 1.0/24., 1.0/120., 1.0/720.,
                                 1.0/5040., 1.0/40320., 1.0/362880.};

__device__ double cgc_fast(int j1, int m1, int j2, int m2, int j3, int m3) {
    if (m1 + m2 != m3) return 0.0;
    int lo = j1 - j2; if (lo < 0) lo = -lo;
    if (j3 < lo || j3 > j1 + j2) return 0.0;
    double pref = sqrt((2.0 * j3 + 1.0) * c_F[j3 + j1 - j2] * c_F[j3 - j1 + j2] *
                       c_F[j1 + j2 - j3] * c_INV[j1 + j2 + j3 + 1]);
    pref *= sqrt(c_F[j3 + m3] * c_F[j3 - m3] * c_F[j1 - m1] * c_F[j1 + m1] *
                 c_F[j2 - m2] * c_F[j2 + m2]);
    double s = 0.0;
    for (int k = 0; k <= j1 + j2 + j3; k++) {
        int d0 = j1 + j2 - j3 - k, d1 = j1 - m1 - k, d2 = j2 + m2 - k;
        int d3 = j3 - j2 + m1 + k, d4 = j3 - j1 - m2 + k;
        if (d0 < 0 || d1 < 0 || d2 < 0 || d3 < 0 || d4 < 0) continue;
        double term = c_INV[k] * c_INV[d0] * c_INV[d1] * c_INV[d2] * c_INV[d3] * c_INV[d4];
        s += (k & 1) ? -term : term;
    }
    return pref * s;
}

__device__ double2 Umat(int l, int i, int a) {
    const double s = 0.70710678118654752440;
    int mi = i - l;
    if (mi == 0) return (a == l) ? make_double2(1.0, 0.0) : make_double2(0.0, 0.0);
    if (mi > 0) {
        int m = mi; double sgn = (m & 1) ? -1.0 : 1.0;
        if (a == l + m) return make_double2(sgn * s, 0.0);
        if (a == l - m) return make_double2(s, 0.0);
    } else {
        int m = -mi; double sgn = (m & 1) ? -1.0 : 1.0;
        if (a == l - m) return make_double2(0.0, s);
        if (a == l + m) return make_double2(0.0, -sgn * s);
    }
    return make_double2(0.0, 0.0);
}

__device__ __forceinline__ float swishf(float x) {
    return x / (1.0f + __expf(-x));
}

// ---------------- fused: CG init + zero accumulators + weight transposes + node_prep ----------------
#define FUSED_BLOCKS 2048
#define PREP_FIRST 63
#define PREP_COUNT 1250

__global__ void __launch_bounds__(256) fused_prep_kernel(
        const float* __restrict__ nf,
        const int* __restrict__ specie,
        const float* __restrict__ Wsc0, const float* __restrict__ Wsc1,
        const float* __restrict__ Wsc2, const float* __restrict__ Wu0,
        const float* __restrict__ Wu1, const float* __restrict__ Wu2,
        const float* __restrict__ Wd0, const float* __restrict__ Wd1,
        const float* __restrict__ Wd2, const float* __restrict__ Wm3,
        float* __restrict__ out) {
    int b = blockIdx.x;
    int t = threadIdx.x;

    if (b >= PREP_FIRST && b < PREP_FIRST + PREP_COUNT) {
        // ---------- node_prep: 4 nodes per block ----------
        __shared__ float sf[4 * 576];
        int nb = (b - PREP_FIRST) * 4;
        {
            const float4* src = (const float4*)(nf + (size_t)nb * 576);
            float4* dst = (float4*)sf;
            for (int i = t; i < 576; i += 256) dst[i] = src[i];
        }
        __syncthreads();

        int g = t & 63;
        int ln = t >> 6;
        int n = nb + ln;
        const float* sfp = sf + ln * 576;
        int sp = specie[n];
        const float* w0p = Wsc0 + sp * 4096;
        const float* w1p = Wsc1 + sp * 4096;
        const float* w2p = Wsc2 + sp * 4096;

        float sc0 = 0.f, g0 = 0.f;
        float sc1[3] = {0.f, 0.f, 0.f}, g1[3] = {0.f, 0.f, 0.f};
        float sc2[5] = {0.f, 0.f, 0.f, 0.f, 0.f}, g2[5] = {0.f, 0.f, 0.f, 0.f, 0.f};
#pragma unroll 4
        for (int f = 0; f < 64; f++) {
            float w0 = w0p[f * 64 + g], u0 = Wu0[f * 64 + g];
            float w1 = w1p[f * 64 + g], u1 = Wu1[f * 64 + g];
            float w2 = w2p[f * 64 + g], u2 = Wu2[f * 64 + g];
            float v0 = sfp[f];
            sc0 = fmaf(v0, w0, sc0);
            g0  = fmaf(v0, u0, g0);
#pragma unroll
            for (int c = 0; c < 3; c++) {
                float v = sfp[64 + f * 3 + c];
                sc1[c] = fmaf(v, w1, sc1[c]);
                g1[c]  = fmaf(v, u1, g1[c]);
            }
#pragma unroll
            for (int c = 0; c < 5; c++) {
                float v = sfp[256 + f * 5 + c];
                sc2[c] = fmaf(v, w2, sc2[c]);
                g2[c]  = fmaf(v, u2, g2[c]);
            }
        }
        const float invF = 0.125f;
        float* orow = out + (size_t)n * 576;
        orow[g] = sc0 * invF;
#pragma unroll
        for (int c = 0; c < 3; c++) orow[64 + g * 3 + c] = sc1[c] * invF;
#pragma unroll
        for (int c = 0; c < 5; c++) orow[256 + g * 5 + c] = sc2[c] * invF;
        g0buf[n * 64 + g] = g0 * invF;
#pragma unroll
        for (int c = 0; c < 3; c++) g1buf[n * 192 + c * 64 + g] = g1[c] * invF;
#pragma unroll
        for (int c = 0; c < 5; c++) g2buf[n * 320 + c * 64 + g] = g2[c] * invF;
        return;
    }

    // ---------- CG (blocks 0..62) ----------
    if (b < PREP_FIRST) {
        int warp_gid = b * 8 + (t >> 5);
        int lane = t & 31;
        if (warp_gid < 504) {
            int idx = warp_gid;
            int l1, l2, l3, flat;
            if (idx < 9)        { l1 = 1; l2 = 1; l3 = 0; flat = idx; }
            else if (idx < 34)  { l1 = 2; l2 = 2; l3 = 0; flat = idx - 9; }
            else if (idx < 79)  { l1 = 1; l2 = 2; l3 = 1; flat = idx - 34; }
            else if (idx < 124) { l1 = 2; l2 = 1; l3 = 1; flat = idx - 79; }
            else if (idx < 229) { l1 = 2; l2 = 3; l3 = 1; flat = idx - 124; }
            else if (idx < 274) { l1 = 1; l2 = 1; l3 = 2; flat = idx - 229; }
            else if (idx < 379) { l1 = 1; l2 = 3; l3 = 2; flat = idx - 274; }
            else                { l1 = 2; l2 = 2; l3 = 2; flat = idx - 379; }
            int dd2 = 2 * l2 + 1, dd3 = 2 * l3 + 1;
            int i = flat / (dd2 * dd3), j = (flat / dd3) % dd2, k = flat % dd3;

            int d1 = 2 * l1 + 1, d2 = 2 * l2 + 1, d3 = 2 * l3 + 1;
            double re = 0.0;
            for (int ab = lane; ab < d1 * d2; ab += 32) {
                int a = ab / d2, bb = ab % d2;
                double2 u1 = Umat(l1, i, a);
                if (u1.x == 0.0 && u1.y == 0.0) continue;
                double2 u2 = Umat(l2, j, bb);
                if (u2.x == 0.0 && u2.y == 0.0) continue;
                double pr = u1.x * u2.x - u1.y * u2.y;
                double pi = u1.x * u2.y + u1.y * u2.x;
                for (int c = 0; c < d3; c++) {
                    double2 u3 = Umat(l3, k, c);
                    u3.y = -u3.y;
                    if (u3.x == 0.0 && u3.y == 0.0) continue;
                    double cg = cgc_fast(l1, a - l1, l2, bb - l2, l3, c - l3);
                    if (cg == 0.0) continue;
                    re += (pr * u3.x - pi * u3.y) * cg;
                }
            }
            __syncwarp();
#pragma unroll
            for (int off = 16; off > 0; off >>= 1)
                re += __shfl_xor_sync(0xffffffffu, re, off);
            if (lane == 0) d_CG[idx] = (float)re;
        }
    }

    // ---------- zero accumulators + weight transposes (blocks 0..62 and 1313..2047) ----------
    int zrank = (b < PREP_FIRST) ? b : (b - PREP_COUNT);
    int zcount = FUSED_BLOCKS - PREP_COUNT;  // 798
    int gid = zrank * 256 + t;
    int stride = zcount * 256;

    // decoder weight interleave
    for (int q = gid; q < 36864; q += stride) {
        int fi = q & 3, tt = (q >> 2) % 192, mo = (q >> 2) / 192;
        wd0t[q] = Wd0[(4 * mo + fi) * 192 + tt];
    }
    for (int q = gid; q < 20480; q += stride) {
        int fi = q & 3, f = (q >> 2) & 63, mo = q >> 8;
        wd1t[q] = Wd1[(4 * mo + fi) * 64 + f];
        wd2t[q] = Wd2[(4 * mo + fi) * 64 + f];
    }
    // Wm3 pair interleave: [((ch*32 + fo)*64 + ft)*2 + fi]
    for (int q = gid; q < 53248; q += stride) {
        int fi = q & 1, ft = (q >> 1) & 63, fo = (q >> 7) & 31, ch = q >> 12;
        wm3t[q] = Wm3[(2 * fo + fi) * 832 + ch * 64 + ft];
    }

    float4* p = reinterpret_cast<float4*>(abuf);
    int n4 = NNODE * 2752 / 4;
    float4 z = make_float4(0.f, 0.f, 0.f, 0.f);
    for (int q = gid; q < n4; q += stride) p[q] = z;
}

// ---------------- edge kernel: R15 structure, Wm3 loads via paired-row LDG.64 ----------------
__global__ void __launch_bounds__(256, 4) edge_kernel(const float* __restrict__ vectors,
                            const int* __restrict__ senders,
                            const int* __restrict__ receivers,
                            const float* __restrict__ Wm1,
                            const float* __restrict__ Wm2) {
    __shared__ float h1[64 * 20];
    __shared__ float h2[64 * 20];
    __shared__ float sT[16 * 104];
    __shared__ float ssh[16 * 16];
    __shared__ float sradT[8 * 16];
    __shared__ float sx[16], sinvx[16];
    __shared__ int ssend[16], srecv[16], sact[16];

    int t = threadIdx.x;
    int ft = t & 63;
    int g = t >> 6;
    int e0 = blockIdx.x * 16;

    if (t < 16) {
        int e = e0 + t;
        float vx = vectors[e * 3 + 0], vy = vectors[e * 3 + 1], vz = vectors[e * 3 + 2];
        float x = sqrtf(fmaxf(vx * vx + vy * vy + vz * vz, 1e-12f));
        float invx = 1.0f / x;
        float ux = vx * invx, uy = vy * invx, uz = vz * invx;
        sx[t] = x; sinvx[t] = invx;
        sact[t] = (x < 1.0f) ? 1 : 0;
        ssend[t] = senders[e];
        srecv[t] = receivers[e];
        float* sh = ssh + t * 16;
        const float s3 = 1.7320508075688772f;
        const float s15 = 3.872983346207417f;
        const float s5 = 2.23606797749979f;
        const float c35 = 2.091650066335189f;
        const float c105 = 10.246950765959598f;
        const float c21 = 1.6201851746019651f;
        const float c7 = 1.3228756555322954f;
        sh[0] = s3 * uy; sh[1] = s3 * uz; sh[2] = s3 * ux;
        sh[3] = s15 * ux * uy;
        sh[4] = s15 * uy * uz;
        sh[5] = 0.5f * s5 * (3.0f * uz * uz - 1.0f);
        sh[6] = s15 * ux * uz;
        sh[7] = 0.5f * s15 * (ux * ux - uy * uy);
        sh[8]  = c35 * uy * (3.0f * ux * ux - uy * uy);
        sh[9]  = c105 * ux * uy * uz;
        sh[10] = c21 * uy * (5.0f * uz * uz - 1.0f);
        sh[11] = c7 * uz * (5.0f * uz * uz - 3.0f);
        sh[12] = c21 * ux * (5.0f * uz * uz - 1.0f);
        sh[13] = 0.5f * c105 * uz * (ux * ux - uy * uy);
        sh[14] = c35 * ux * (ux * ux - 3.0f * uy * uy);
        sh[15] = 0.f;
    }
    __syncthreads();

    if (t < 128) {
        int e = t & 15, n = t >> 4;
        float x = sx[e];
        float env = 0.f;
        if (x < 1.0f) {
            float x2 = x * x, x4 = x2 * x2, x6 = x4 * x2, x7 = x6 * x, x8 = x7 * x;
            env = 1.0f - 28.0f * x6 + 48.0f * x7 - 21.0f * x8;
        }
        float nn = (float)(n + 1);
        sradT[n * 16 + e] = 1.41421356237f * sinf(3.14159265358979f * nn * x) * sinvx[e] * env;
    }
    __syncthreads();

    for (int idx = t; idx < 16 * 102; idx += 256) {
        int e = idx / 102, j = idx % 102;
        const float* sh = ssh + e * 16;
        float v = 0.f;
        if (j < 3) {
            int i = j;
            for (int q = 0; q < 3; q++) v = fmaf(sh[q], d_CG[OFF110 + i * 3 + q], v);
        } else if (j < 8) {
            int i = j - 3;
            for (int q = 0; q < 5; q++) v = fmaf(sh[3 + q], d_CG[OFF220 + i * 5 + q], v);
        } else if (j < 17) {
            int ee = j - 8; int i = ee / 3, k = ee % 3;
            for (int q = 0; q < 5; q++) v = fmaf(sh[3 + q], d_CG[OFF121 + (i * 5 + q) * 3 + k], v);
        } else if (j < 32) {
            int ee = j - 17; int i = ee / 3, k = ee % 3;
            for (int q = 0; q < 3; q++) v = fmaf(sh[q], d_CG[OFF211 + (i * 3 + q) * 3 + k], v);
        } else if (j < 47) {
            int ee = j - 32; int i = ee / 3, k = ee % 3;
            for (int q = 0; q < 7; q++) v = fmaf(sh[8 + q], d_CG[OFF231 + (i * 7 + q) * 3 + k], v);
        } else if (j < 62) {
            int ee = j - 47; int i = ee / 5, k = ee % 5;
            for (int q = 0; q < 3; q++) v = fmaf(sh[q], d_CG[OFF112 + (i * 3 + q) * 5 + k], v);
        } else if (j < 77) {
            int ee = j - 62; int i = ee / 5, k = ee % 5;
            for (int q = 0; q < 7; q++) v = fmaf(sh[8 + q], d_CG[OFF132 + (i * 7 + q) * 5 + k], v);
        } else {
            int ee = j - 77; int i = ee / 5, k = ee % 5;
            for (int q = 0; q < 5; q++) v = fmaf(sh[3 + q], d_CG[OFF222 + (i * 5 + q) * 5 + k], v);
        }
        sT[e * 104 + j] = v;
    }
    __syncthreads();

    {
        float a0 = 0.f, a1 = 0.f, a2 = 0.f, a3 = 0.f;
#pragma unroll
        for (int i = 0; i < 8; i++) {
            float w = Wm1[i * 64 + ft];
            float4 r = *(const float4*)(sradT + i * 16 + 4 * g);
            a0 = fmaf(r.x, w, a0); a1 = fmaf(r.y, w, a1);
            a2 = fmaf(r.z, w, a2); a3 = fmaf(r.w, w, a3);
        }
        const float s8 = 0.35355339059327f;
        h1[ft * 20 + 4 * g + 0] = swishf(a0 * s8);
        h1[ft * 20 + 4 * g + 1] = swishf(a1 * s8);
        h1[ft * 20 + 4 * g + 2] = swishf(a2 * s8);
        h1[ft * 20 + 4 * g + 3] = swishf(a3 * s8);
    }
    __syncthreads();

    {
        float a0 = 0.f, a1 = 0.f, a2 = 0.f, a3 = 0.f;
#pragma unroll 8
        for (int f = 0; f < 64; f++) {
            float w = Wm2[f * 64 + ft];
            float4 hv = *(const float4*)(h1 + f * 20 + 4 * g);
            a0 = fmaf(hv.x, w, a0); a1 = fmaf(hv.y, w, a1);
            a2 = fmaf(hv.z, w, a2); a3 = fmaf(hv.w, w, a3);
        }
        const float s64 = 0.125f;
        h2[ft * 20 + 4 * g + 0] = swishf(a0 * s64);
        h2[ft * 20 + 4 * g + 1] = swishf(a1 * s64);
        h2[ft * 20 + 4 * g + 2] = swishf(a2 * s64);
        h2[ft * 20 + 4 * g + 3] = swishf(a3 * s64);
    }
    __syncthreads();

    const float msc = 0.125f * 0.316227766016838f;
    const float2* wt2 = (const float2*)wm3t;  // [(ch*32+fo)*64 + ft]

    // PASS A: channels {0,1,3,4,5,9,10,11} (s0/s1)
    {
        float acc[8][4];
#pragma unroll
        for (int q = 0; q < 8; q++)
#pragma unroll
            for (int el = 0; el < 4; el++) acc[q][el] = 0.f;
#pragma unroll 2
        for (int fo = 0; fo < 32; fo++) {
            float4 hv0 = *(const float4*)(h2 + (2 * fo + 0) * 20 + 4 * g);
            float4 hv1 = *(const float4*)(h2 + (2 * fo + 1) * 20 + 4 * g);
            const float2* wb = wt2 + fo * 64 + ft;
            float2 w2;
#define FMA8(Q, CH)                                                 \
            w2 = wb[(CH) * 2048];                                   \
            acc[Q][0] = fmaf(hv0.x, w2.x, acc[Q][0]);               \
            acc[Q][1] = fmaf(hv0.y, w2.x, acc[Q][1]);               \
            acc[Q][2] = fmaf(hv0.z, w2.x, acc[Q][2]);               \
            acc[Q][3] = fmaf(hv0.w, w2.x, acc[Q][3]);               \
            acc[Q][0] = fmaf(hv1.x, w2.y, acc[Q][0]);               \
            acc[Q][1] = fmaf(hv1.y, w2.y, acc[Q][1]);               \
            acc[Q][2] = fmaf(hv1.z, w2.y, acc[Q][2]);               \
            acc[Q][3] = fmaf(hv1.w, w2.y, acc[Q][3]);
            FMA8(0, 0) FMA8(1, 1) FMA8(2, 3) FMA8(3, 4)
            FMA8(4, 5) FMA8(5, 9) FMA8(6, 10) FMA8(7, 11)
#undef FMA8
        }
#pragma unroll
        for (int q = 0; q < 8; q++)
#pragma unroll
            for (int el = 0; el < 4; el++) acc[q][el] *= msc;

#pragma unroll
        for (int el = 0; el < 4; el++) {
            int e = 4 * g + el;
            if (!sact[e]) continue;
            int sn = ssend[e];
            float* ap = abuf + (size_t)srecv[e] * 2752;
            const float* T = sT + e * 104;
            const float* sh = ssh + e * 16;
            float s0v = g0buf[sn * 64 + ft];
            float s1a = g1buf[sn * 192 + 0 * 64 + ft];
            float s1b = g1buf[sn * 192 + 1 * 64 + ft];
            float s1c = g1buf[sn * 192 + 2 * 64 + ft];

            atomicAdd(ap + ft, s0v * acc[0][el]);
            float tp110 = s1a * T[0] + s1b * T[1] + s1c * T[2];
            atomicAdd(ap + 64 + ft, tp110 * acc[1][el]);
#pragma unroll
            for (int c = 0; c < 3; c++) {
                float* p = ap + 192 + c * 320;
                float s1cc = (c == 0) ? s1a : ((c == 1) ? s1b : s1c);
                atomicAdd(p + ft, s1cc * acc[2][el]);
                atomicAdd(p + 64 + ft, s0v * sh[c] * acc[3][el]);
                float t121 = s1a * T[8 + c] + s1b * T[11 + c] + s1c * T[14 + c];
                atomicAdd(p + 128 + ft, t121 * acc[4][el]);
            }
#pragma unroll
            for (int c = 0; c < 5; c++) {
                float* p = ap + 1152 + c * 320;
                atomicAdd(p + 64 + ft, s0v * sh[3 + c] * acc[5][el]);
                float t112 = s1a * T[47 + c] + s1b * T[52 + c] + s1c * T[57 + c];
                atomicAdd(p + 128 + ft, t112 * acc[6][el]);
                float t132 = s1a * T[62 + c] + s1b * T[67 + c] + s1c * T[72 + c];
                atomicAdd(p + 192 + ft, t132 * acc[7][el]);
            }
        }
    }

    // PASS B: channels {2,6,7,8,12} (s2)
    {
        float acc[5][4];
#pragma unroll
        for (int q = 0; q < 5; q++)
#pragma unroll
            for (int el = 0; el < 4; el++) acc[q][el] = 0.f;
#pragma unroll 2
        for (int fo = 0; fo < 32; fo++) {
            float4 hv0 = *(const float4*)(h2 + (2 * fo + 0) * 20 + 4 * g);
            float4 hv1 = *(const float4*)(h2 + (2 * fo + 1) * 20 + 4 * g);
            const float2* wb = wt2 + fo * 64 + ft;
            float2 w2;
#define FMA8(Q, CH)                                                 \
            w2 = wb[(CH) * 2048];                                   \
            acc[Q][0] = fmaf(hv0.x, w2.x, acc[Q][0]);               \
            acc[Q][1] = fmaf(hv0.y, w2.x, acc[Q][1]);               \
            acc[Q][2] = fmaf(hv0.z, w2.x, acc[Q][2]);               \
            acc[Q][3] = fmaf(hv0.w, w2.x, acc[Q][3]);               \
            acc[Q][0] = fmaf(hv1.x, w2.y, acc[Q][0]);               \
            acc[Q][1] = fmaf(hv1.y, w2.y, acc[Q][1]);               \
            acc[Q][2] = fmaf(hv1.z, w2.y, acc[Q][2]);               \
            acc[Q][3] = fmaf(hv1.w, w2.y, acc[Q][3]);
            FMA8(0, 2) FMA8(1, 6) FMA8(2, 7) FMA8(3, 8) FMA8(4, 12)
#undef FMA8
        }
#pragma unroll
        for (int q = 0; q < 5; q++)
#pragma unroll
            for (int el = 0; el < 4; el++) acc[q][el] *= msc;

#pragma unroll
        for (int el = 0; el < 4; el++) {
            int e = 4 * g + el;
            if (!sact[e]) continue;
            int sn = ssend[e];
            float* ap = abuf + (size_t)srecv[e] * 2752;
            const float* T = sT + e * 104;
            float s2v[5];
#pragma unroll
            for (int c = 0; c < 5; c++) s2v[c] = g2buf[sn * 320 + c * 64 + ft];

            float tp220 = 0.f;
#pragma unroll
            for (int i = 0; i < 5; i++) tp220 = fmaf(s2v[i], T[3 + i], tp220);
            atomicAdd(ap + 128 + ft, tp220 * acc[0][el]);

#pragma unroll
            for (int c = 0; c < 3; c++) {
                float* p = ap + 192 + c * 320;
                float t211 = 0.f, t231 = 0.f;
#pragma unroll
                for (int i = 0; i < 5; i++) {
                    t211 = fmaf(s2v[i], T[17 + i * 3 + c], t211);
                    t231 = fmaf(s2v[i], T[32 + i * 3 + c], t231);
                }
                atomicAdd(p + 192 + ft, t211 * acc[1][el]);
                atomicAdd(p + 256 + ft, t231 * acc[2][el]);
            }
#pragma unroll
            for (int c = 0; c < 5; c++) {
                float* p = ap + 1152 + c * 320;
                atomicAdd(p + ft, s2v[c] * acc[3][el]);
                float t222 = 0.f;
#pragma unroll
                for (int i = 0; i < 5; i++) t222 = fmaf(s2v[i], T[77 + i * 5 + c], t222);
                atomicAdd(p + 256 + ft, t222 * acc[4][el]);
            }
        }
    }
}

// ---------------- node output v3: 4 nodes / block, vectorized weight loads (R15 proven) ----------------
__global__ void __launch_bounds__(320) node_out_kernel(float* __restrict__ out) {
    int n0 = blockIdx.x * 4;
    int t = threadIdx.x;
    __shared__ float saT[2752 * 4];
    __shared__ float sd0[4 * 192];

    for (int j = t; j < 2752; j += 320) {
#pragma unroll
        for (int nn = 0; nn < 4; nn++)
            saT[j * 4 + nn] = abuf[(size_t)(n0 + nn) * 2752 + j];
    }
    __syncthreads();

    if (t < 192) {
        float a0 = 0.f, a1 = 0.f, a2 = 0.f, a3 = 0.f;
        const float4* wb = ((const float4*)wd0t) + t;
#pragma unroll 4
        for (int mo = 0; mo < 48; mo++) {
            float4 w4 = wb[mo * 192];
            const float* base = saT + mo * 16;
            float4 v0 = *(const float4*)(base);
            float4 v1 = *(const float4*)(base + 4);
            float4 v2 = *(const float4*)(base + 8);
            float4 v3 = *(const float4*)(base + 12);
            a0 = fmaf(v0.x, w4.x, a0); a1 = fmaf(v0.y, w4.x, a1);
            a2 = fmaf(v0.z, w4.x, a2); a3 = fmaf(v0.w, w4.x, a3);
            a0 = fmaf(v1.x, w4.y, a0); a1 = fmaf(v1.y, w4.y, a1);
            a2 = fmaf(v1.z, w4.y, a2); a3 = fmaf(v1.w, w4.y, a3);
            a0 = fmaf(v2.x, w4.z, a0); a1 = fmaf(v2.y, w4.z, a1);
            a2 = fmaf(v2.z, w4.z, a2); a3 = fmaf(v2.w, w4.z, a3);
            a0 = fmaf(v3.x, w4.w, a0); a1 = fmaf(v3.y, w4.w, a1);
            a2 = fmaf(v3.z, w4.w, a2); a3 = fmaf(v3.w, w4.w, a3);
        }
        const float s = 0.0721687836487032f;
        sd0[0 * 192 + t] = swishf(a0 * s);
        sd0[1 * 192 + t] = swishf(a1 * s);
        sd0[2 * 192 + t] = swishf(a2 * s);
        sd0[3 * 192 + t] = swishf(a3 * s);
    }
    __syncthreads();

    if (t < 64) {
#pragma unroll
        for (int nn = 0; nn < 4; nn++)
            out[(size_t)(n0 + nn) * 576 + t] += sd0[nn * 192 + t];
    }

    const float s320 = 0.0559016994374947f;

    if (t < 192) {
        int c = t / 64, f = t % 64;
        float a0 = 0.f, a1 = 0.f, a2 = 0.f, a3 = 0.f;
        const float4* wb = ((const float4*)wd1t) + f;
        const float* sbase = saT + (192 + c * 320) * 4;
#pragma unroll 4
        for (int mo = 0; mo < 80; mo++) {
            float4 w4 = wb[mo * 64];
            const float* base = sbase + mo * 16;
            float4 v0 = *(const float4*)(base);
            float4 v1 = *(const float4*)(base + 4);
            float4 v2 = *(const float4*)(base + 8);
            float4 v3 = *(const float4*)(base + 12);
            a0 = fmaf(v0.x, w4.x, a0); a1 = fmaf(v0.y, w4.x, a1);
            a2 = fmaf(v0.z, w4.x, a2); a3 = fmaf(v0.w, w4.x, a3);
            a0 = fmaf(v1.x, w4.y, a0); a1 = fmaf(v1.y, w4.y, a1);
            a2 = fmaf(v1.z, w4.y, a2); a3 = fmaf(v1.w, w4.y, a3);
            a0 = fmaf(v2.x, w4.z, a0); a1 = fmaf(v2.y, w4.z, a1);
            a2 = fmaf(v2.z, w4.z, a2); a3 = fmaf(v2.w, w4.z, a3);
            a0 = fmaf(v3.x, w4.w, a0); a1 = fmaf(v3.y, w4.w, a1);
            a2 = fmaf(v3.z, w4.w, a2); a3 = fmaf(v3.w, w4.w, a3);
        }
        float r[4] = {a0, a1, a2, a3};
#pragma unroll
        for (int nn = 0; nn < 4; nn++)
            out[(size_t)(n0 + nn) * 576 + 64 + f * 3 + c] += r[nn] * s320 * sd0[nn * 192 + 64 + f];
    }

    {
        int c = t / 64, f = t % 64;
        float a0 = 0.f, a1 = 0.f, a2 = 0.f, a3 = 0.f;
        const float4* wb = ((const float4*)wd2t) + f;
        const float* sbase = saT + (1152 + c * 320) * 4;
#pragma unroll 4
        for (int mo = 0; mo < 80; mo++) {
            float4 w4 = wb[mo * 64];
            const float* base = sbase + mo * 16;
            float4 v0 = *(const float4*)(base);
            float4 v1 = *(const float4*)(base + 4);
            float4 v2 = *(const float4*)(base + 8);
            float4 v3 = *(const float4*)(base + 12);
            a0 = fmaf(v0.x, w4.x, a0); a1 = fmaf(v0.y, w4.x, a1);
            a2 = fmaf(v0.z, w4.x, a2); a3 = fmaf(v0.w, w4.x, a3);
            a0 = fmaf(v1.x, w4.y, a0); a1 = fmaf(v1.y, w4.y, a1);
            a2 = fmaf(v1.z, w4.y, a2); a3 = fmaf(v1.w, w4.y, a3);
            a0 = fmaf(v2.x, w4.z, a0); a1 = fmaf(v2.y, w4.z, a1);
            a2 = fmaf(v2.z, w4.z, a2); a3 = fmaf(v2.w, w4.z, a3);
            a0 = fmaf(v3.x, w4.w, a0); a1 = fmaf(v3.y, w4.w, a1);
            a2 = fmaf(v3.z, w4.w, a2); a3 = fmaf(v3.w, w4.w, a3);
        }
        float r[4] = {a0, a1, a2, a3};
#pragma unroll
        for (int nn = 0; nn < 4; nn++)
            out[(size_t)(n0 + nn) * 576 + 256 + f * 5 + c] += r[nn] * s320 * sd0[nn * 192 + 128 + f];
    }
}

// ---------------- launcher ----------------
extern "C" void kernel_launch(void* const* d_in, const int* in_sizes, int n_in,
                              void* d_out, int out_size) {
    const float* vectors    = (const float*)d_in[0];
    const float* node_feats = (const float*)d_in[1];
    const int*   node_specie= (const int*)d_in[2];
    const int*   senders    = (const int*)d_in[3];
    const int*   receivers  = (const int*)d_in[4];
    const float* Wsc0 = (const float*)d_in[5];
    const float* Wsc1 = (const float*)d_in[6];
    const float* Wsc2 = (const float*)d_in[7];
    const float* Wu0  = (const float*)d_in[8];
    const float* Wu1  = (const float*)d_in[9];
    const float* Wu2  = (const float*)d_in[10];
    const float* Wm1  = (const float*)d_in[11];
    const float* Wm2  = (const float*)d_in[12];
    const float* Wm3  = (const float*)d_in[13];
    const float* Wd0  = (const float*)d_in[14];
    const float* Wd1  = (const float*)d_in[15];
    const float* Wd2  = (const float*)d_in[16];
    float* out = (float*)d_out;

    fused_prep_kernel<<<FUSED_BLOCKS, 256>>>(node_feats, node_specie,
                                             Wsc0, Wsc1, Wsc2, Wu0, Wu1, Wu2,
                                             Wd0, Wd1, Wd2, Wm3, out);
    edge_kernel<<<NEDGE / 16, 256>>>(vectors, senders, receivers, Wm1, Wm2);
    node_out_kernel<<<NNODE / 4, 320>>>(out);
}